// round 3
// baseline (speedup 1.0000x reference)
#include <cuda_runtime.h>
#include <stdint.h>

#define NF 16384
#define NB 4096
#define EF 262144
#define EB 65536
#define EFPAD (EF + 64*8)      // 262656, bucket regions padded to multiples of 8
#define NTILES (EFPAD/8)       // 32832

// ---------------- scratch (__device__ globals; no runtime allocation) ----------------
__device__ __align__(16) float g_ans96 [NF*96];
__device__ __align__(16) float g_ans64a[NF*64];
__device__ __align__(16) float g_ans64b[NF*64];
__device__ __align__(16) float g_acc64a[NF*64];
__device__ __align__(16) float g_acc64b[NF*64];
__device__ __align__(16) float g_acc2  [NF*2];
__device__ __align__(16) float4 g_few[EF];
__device__ int   g_febkt[EF];
__device__ __align__(16) float4 g_bew[EB];
__device__ int   g_bbkt[EB];
__device__ int   g_bcnt[64];
__device__ int   g_boff[65];
__device__ int   g_bcur[64];
__device__ int   g_blist[EFPAD];
__device__ int   g_tilebkt[NTILES];

// ---------------- init: zero accumulators, clear edge list ----------------
__global__ void k_init() {
    int i  = blockIdx.x * blockDim.x + threadIdx.x;
    int st = gridDim.x * blockDim.x;
    for (int k = i; k < NF*96; k += st) g_ans96[k] = 0.f;
    for (int k = i; k < NF*64; k += st) { g_acc64a[k] = 0.f; g_acc64b[k] = 0.f; }
    for (int k = i; k < NF*2;  k += st) g_acc2[k] = 0.f;
    for (int k = i; k < EFPAD; k += st) g_blist[k] = -1;
    if (i < 64) g_bcnt[i] = 0;
}

// ---------------- edge basis: tent weights + base cell ----------------
__device__ __forceinline__ void edge_basis(float dx, float dy, int* bkt, float4* w) {
    // polar map: (2r-1, theta/pi), tent basis on 8 centers spanning [-1,1]
    float r  = sqrtf(dx*dx + dy*dy + 1e-12f);
    float u  = 2.f*r - 1.f;
    float v  = atan2f(dy, dx) * 0.3183098861837907f;   // 1/pi
    float tu = (u + 1.f) * 3.5f;                       // (u+1)/spacing, spacing=2/7
    float tv = (v + 1.f) * 3.5f;
    int iu = (int)floorf(tu); iu = max(0, min(7, iu));
    int iv = (int)floorf(tv); iv = max(0, min(7, iv));
    float wu0 = fmaxf(0.f, 1.f - fabsf(tu - (float)iu));
    float wu1 = (iu < 7) ? fmaxf(0.f, 1.f - fabsf(tu - (float)(iu+1))) : 0.f;
    float wv0 = fmaxf(0.f, 1.f - fabsf(tv - (float)iv));
    float wv1 = (iv < 7) ? fmaxf(0.f, 1.f - fabsf(tv - (float)(iv+1))) : 0.f;
    *bkt = iu*8 + iv;
    *w = make_float4(wu0*wv0, wu0*wv1, wu1*wv0, wu1*wv1);
}

__global__ void k_prep_fluid(const float* __restrict__ fp,
                             const int* __restrict__ fi, const int* __restrict__ fj,
                             const float* __restrict__ supp) {
    int e = blockIdx.x * blockDim.x + threadIdx.x;
    if (e >= EF) return;
    float s = __ldg(supp);
    int a = fi[e], b = fj[e];
    float dx = -(fp[b*2+0] - fp[a*2+0]) / s;
    float dy = -(fp[b*2+1] - fp[a*2+1]) / s;
    dx = fminf(1.f, fmaxf(-1.f, dx));
    dy = fminf(1.f, fmaxf(-1.f, dy));
    int bkt; float4 w;
    edge_basis(dx, dy, &bkt, &w);
    g_few[e] = w;
    g_febkt[e] = bkt;
    atomicAdd(&g_bcnt[bkt], 1);
}

__global__ void k_prep_bdy(const float* __restrict__ fp, const float* __restrict__ bp,
                           const int* __restrict__ bfi, const int* __restrict__ bbi,
                           const float* __restrict__ supp) {
    int e = blockIdx.x * blockDim.x + threadIdx.x;
    if (e >= EB) return;
    float s = __ldg(supp);
    int a = bfi[e], b = bbi[e];   // target fluid, source boundary
    float dx = (bp[b*2+0] - fp[a*2+0]) / s;
    float dy = (bp[b*2+1] - fp[a*2+1]) / s;
    dx = fminf(1.f, fmaxf(-1.f, dx));
    dy = fminf(1.f, fmaxf(-1.f, dy));
    int bkt; float4 w;
    edge_basis(dx, dy, &bkt, &w);
    g_bew[e] = w;
    g_bbkt[e] = bkt;
}

// ---------------- bucket scan (padded to 8) + fill sorted edge list ----------------
__global__ void k_scan() {
    if (threadIdx.x == 0 && blockIdx.x == 0) {
        int off = 0;
        for (int b = 0; b < 64; b++) {
            g_boff[b] = off;
            g_bcur[b] = off;
            off += (g_bcnt[b] + 7) & ~7;
        }
        g_boff[64] = off;
    }
}

__global__ void k_fill() {
    int e = blockIdx.x * blockDim.x + threadIdx.x;
    if (e >= EF) return;
    int bkt = g_febkt[e];
    int pos = atomicAdd(&g_bcur[bkt], 1);
    g_blist[pos] = e;
    g_tilebkt[pos >> 3] = bkt;   // benign race: same value per tile
}

// ---------------- dense lin: ans96[:,0:32] = relu(ff @ fc0) ----------------
__global__ void k_lin(const float* __restrict__ ff, const float* __restrict__ fc0) {
    int n = blockIdx.x * blockDim.x + threadIdx.x;
    if (n >= NF) return;
    float4 x = *reinterpret_cast<const float4*>(ff + n*4);
    float* o = g_ans96 + n*96;
    #pragma unroll
    for (int co = 0; co < 32; co++) {
        float a = x.x*__ldg(fc0+co) + x.y*__ldg(fc0+32+co)
                + x.z*__ldg(fc0+64+co) + x.w*__ldg(fc0+96+co);
        o[co] = fmaxf(a, 0.f);
    }
}

// ---------------- small conv (cin=4, cout=32): per-edge, W fully L1-resident ----------------
__global__ void k_conv_small(const float* __restrict__ x, const float* __restrict__ W,
                             const int* __restrict__ tgt, const int* __restrict__ src,
                             int E, int dstOff, int isBdy) {
    int e = blockIdx.x * blockDim.x + threadIdx.x;
    if (e >= E) return;
    int bkt  = isBdy ? g_bbkt[e] : g_febkt[e];
    float4 w = isBdy ? g_bew[e]  : g_few[e];
    int iu = bkt >> 3, iv = bkt & 7;
    int iu1 = min(iu+1, 7), iv1 = min(iv+1, 7);
    int cells[4] = { iu*8+iv, iu*8+iv1, iu1*8+iv, iu1*8+iv1 };
    float wc[4] = { w.x, w.y, w.z, w.w };
    float4 xv = *reinterpret_cast<const float4*>(x + src[e]*4);
    float acc[32];
    #pragma unroll
    for (int co = 0; co < 32; co++) acc[co] = 0.f;
    #pragma unroll
    for (int c = 0; c < 4; c++) {
        const float* Wc = W + cells[c]*128;   // [cell][cin=4][cout=32]
        float s0 = wc[c]*xv.x, s1 = wc[c]*xv.y, s2 = wc[c]*xv.z, s3 = wc[c]*xv.w;
        #pragma unroll
        for (int co = 0; co < 32; co++)
            acc[co] += s0*__ldg(Wc+co) + s1*__ldg(Wc+32+co)
                     + s2*__ldg(Wc+64+co) + s3*__ldg(Wc+96+co);
    }
    float* o = g_ans96 + tgt[e]*96 + dstOff;
    #pragma unroll
    for (int co = 0; co < 32; co++) atomicAdd(o + co, acc[co]);
}

// relu on ans96 columns 32..95 (conv parts) after accumulation
__global__ void k_relu96() {
    int i = blockIdx.x * blockDim.x + threadIdx.x;
    if (i >= NF*64) return;
    int n = i >> 6, c = i & 63;
    float* p = g_ans96 + n*96 + 32 + c;
    *p = fmaxf(*p, 0.f);
}

// ---------------- big conv (cout=64): bucketed warp tiles of 8 edges ----------------
template<int CIN>
__global__ void __launch_bounds__(256) k_conv_big(const float* __restrict__ W,
                                                  const int* __restrict__ fi,
                                                  const int* __restrict__ fj) {
    const float* x;
    float* out;
    if (CIN == 96) { x = g_ans96;  out = g_acc64a; }
    else           { x = g_ans64a; out = g_acc64b; }

    __shared__ __align__(16) float xs[8][CIN*8];   // [warp][cin*8 + e], transposed x
    __shared__ __align__(16) float ws[8][4][8];    // [warp][cell][e] cell weights

    int warp = threadIdx.x >> 5, lane = threadIdx.x & 31;
    int tile = blockIdx.x * 8 + warp;              // tile < NTILES by grid sizing

    int eid = -1, srcv = -1, tgtv = -1;
    if (lane < 8) eid = g_blist[tile*8 + lane];
    bool valid = (lane < 8) && (eid >= 0);
    if (valid) { srcv = fj[eid]; tgtv = fi[eid]; }
    if (lane < 8) {
        float4 w = valid ? g_few[eid] : make_float4(0.f, 0.f, 0.f, 0.f);
        ws[warp][0][lane] = w.x; ws[warp][1][lane] = w.y;
        ws[warp][2][lane] = w.z; ws[warp][3][lane] = w.w;
    }
    unsigned vmask = __ballot_sync(0xffffffffu, valid);
    if (vmask == 0u) return;                       // all-dummy tile

    int bkt = g_tilebkt[tile];
    bkt = max(0, min(63, bkt));

    int src[8];
    #pragma unroll
    for (int e = 0; e < 8; e++) src[e] = __shfl_sync(0xffffffffu, srcv, e);

    // stage x transposed: xs[cin*8 + e]
    for (int i = lane; i < CIN*8; i += 32) {
        int cin = i >> 3, e = i & 7;
        int s = src[e];
        xs[warp][cin*8 + e] = (s >= 0) ? __ldg(x + s*CIN + cin) : 0.f;
    }
    __syncwarp();

    int iu = bkt >> 3, iv = bkt & 7;
    int iu1 = min(iu+1, 7), iv1 = min(iv+1, 7);
    int cellIdx[4] = { iu*8+iv, iu*8+iv1, iu1*8+iv, iu1*8+iv1 };

    float acc[8][2];
    #pragma unroll
    for (int e = 0; e < 8; e++) { acc[e][0] = 0.f; acc[e][1] = 0.f; }

    const float* xsw = xs[warp];
    #pragma unroll
    for (int c = 0; c < 4; c++) {
        const float* Wc = W + cellIdx[c]*(CIN*64) + lane*2;   // lane -> 2 couts
        float tmp[8][2];
        #pragma unroll
        for (int e = 0; e < 8; e++) { tmp[e][0] = 0.f; tmp[e][1] = 0.f; }
        #pragma unroll 4
        for (int cin = 0; cin < CIN; cin++) {
            float2 wv = __ldg(reinterpret_cast<const float2*>(Wc + cin*64));
            float4 xa = *reinterpret_cast<const float4*>(xsw + cin*8);
            float4 xb = *reinterpret_cast<const float4*>(xsw + cin*8 + 4);
            tmp[0][0] = fmaf(xa.x, wv.x, tmp[0][0]); tmp[0][1] = fmaf(xa.x, wv.y, tmp[0][1]);
            tmp[1][0] = fmaf(xa.y, wv.x, tmp[1][0]); tmp[1][1] = fmaf(xa.y, wv.y, tmp[1][1]);
            tmp[2][0] = fmaf(xa.z, wv.x, tmp[2][0]); tmp[2][1] = fmaf(xa.z, wv.y, tmp[2][1]);
            tmp[3][0] = fmaf(xa.w, wv.x, tmp[3][0]); tmp[3][1] = fmaf(xa.w, wv.y, tmp[3][1]);
            tmp[4][0] = fmaf(xb.x, wv.x, tmp[4][0]); tmp[4][1] = fmaf(xb.x, wv.y, tmp[4][1]);
            tmp[5][0] = fmaf(xb.y, wv.x, tmp[5][0]); tmp[5][1] = fmaf(xb.y, wv.y, tmp[5][1]);
            tmp[6][0] = fmaf(xb.z, wv.x, tmp[6][0]); tmp[6][1] = fmaf(xb.z, wv.y, tmp[6][1]);
            tmp[7][0] = fmaf(xb.w, wv.x, tmp[7][0]); tmp[7][1] = fmaf(xb.w, wv.y, tmp[7][1]);
        }
        float4 wA = *reinterpret_cast<const float4*>(&ws[warp][c][0]);
        float4 wB = *reinterpret_cast<const float4*>(&ws[warp][c][4]);
        float wcell[8] = { wA.x, wA.y, wA.z, wA.w, wB.x, wB.y, wB.z, wB.w };
        #pragma unroll
        for (int e = 0; e < 8; e++) {
            acc[e][0] = fmaf(wcell[e], tmp[e][0], acc[e][0]);
            acc[e][1] = fmaf(wcell[e], tmp[e][1], acc[e][1]);
        }
    }
    #pragma unroll
    for (int e = 0; e < 8; e++) {
        int t = __shfl_sync(0xffffffffu, tgtv, e);
        if (t >= 0) {
            atomicAdd(out + t*64 + lane*2,     acc[e][0]);
            atomicAdd(out + t*64 + lane*2 + 1, acc[e][1]);
        }
    }
}

// ---------------- W4 conv (cin=64, cout=2): per-edge, W fully L1-resident ----------------
__global__ void k_conv_w4(const float* __restrict__ W4,
                          const int* __restrict__ fi, const int* __restrict__ fj) {
    int e = blockIdx.x * blockDim.x + threadIdx.x;
    if (e >= EF) return;
    int bkt = g_febkt[e]; float4 w = g_few[e];
    int iu = bkt >> 3, iv = bkt & 7;
    int iu1 = min(iu+1, 7), iv1 = min(iv+1, 7);
    const float* Wc0 = W4 + (iu*8+iv)*128;    // [cell][cin=64][cout=2]
    const float* Wc1 = W4 + (iu*8+iv1)*128;
    const float* Wc2 = W4 + (iu1*8+iv)*128;
    const float* Wc3 = W4 + (iu1*8+iv1)*128;
    const float* x = g_ans64b + fj[e]*64;
    float t00=0.f,t01=0.f,t10=0.f,t11=0.f,t20=0.f,t21=0.f,t30=0.f,t31=0.f;
    #pragma unroll 8
    for (int cin = 0; cin < 64; cin++) {
        float xv = __ldg(x + cin);
        float2 a = __ldg(reinterpret_cast<const float2*>(Wc0 + cin*2));
        float2 b = __ldg(reinterpret_cast<const float2*>(Wc1 + cin*2));
        float2 c = __ldg(reinterpret_cast<const float2*>(Wc2 + cin*2));
        float2 d = __ldg(reinterpret_cast<const float2*>(Wc3 + cin*2));
        t00 = fmaf(xv, a.x, t00); t01 = fmaf(xv, a.y, t01);
        t10 = fmaf(xv, b.x, t10); t11 = fmaf(xv, b.y, t11);
        t20 = fmaf(xv, c.x, t20); t21 = fmaf(xv, c.y, t21);
        t30 = fmaf(xv, d.x, t30); t31 = fmaf(xv, d.y, t31);
    }
    float a0 = w.x*t00 + w.y*t10 + w.z*t20 + w.w*t30;
    float a1 = w.x*t01 + w.y*t11 + w.z*t21 + w.w*t31;
    int t = fi[e];
    atomicAdd(g_acc2 + t*2,     a0);
    atomicAdd(g_acc2 + t*2 + 1, a1);
}

// ---------------- dense epilogues (warp per node) ----------------
__global__ void k_postB(const float* __restrict__ fc1) {
    int warp = threadIdx.x >> 5, lane = threadIdx.x & 31;
    int n = blockIdx.x * 8 + warp;
    const float* xrow = g_ans96 + n*96;
    float a0 = 0.f, a1 = 0.f;
    #pragma unroll
    for (int k = 0; k < 96; k += 32) {
        float xv = xrow[k + lane];
        #pragma unroll
        for (int j = 0; j < 32; j++) {
            float xj = __shfl_sync(0xffffffffu, xv, j);
            float2 f = __ldg(reinterpret_cast<const float2*>(fc1 + (k+j)*64 + lane*2));
            a0 = fmaf(xj, f.x, a0); a1 = fmaf(xj, f.y, a1);
        }
    }
    float2 c = *reinterpret_cast<const float2*>(g_acc64a + n*64 + lane*2);
    float* o = g_ans64a + n*64 + lane*2;
    o[0] = fmaxf(c.x + a0, 0.f);
    o[1] = fmaxf(c.y + a1, 0.f);
}

__global__ void k_postC(const float* __restrict__ fc2) {
    int warp = threadIdx.x >> 5, lane = threadIdx.x & 31;
    int n = blockIdx.x * 8 + warp;
    const float* xrow = g_ans64a + n*64;
    float a0 = 0.f, a1 = 0.f;
    #pragma unroll
    for (int k = 0; k < 64; k += 32) {
        float xv = xrow[k + lane];
        #pragma unroll
        for (int j = 0; j < 32; j++) {
            float xj = __shfl_sync(0xffffffffu, xv, j);
            float2 f = __ldg(reinterpret_cast<const float2*>(fc2 + (k+j)*64 + lane*2));
            a0 = fmaf(xj, f.x, a0); a1 = fmaf(xj, f.y, a1);
        }
    }
    float2 c  = *reinterpret_cast<const float2*>(g_acc64b + n*64 + lane*2);
    float2 xr = *reinterpret_cast<const float2*>(g_ans64a + n*64 + lane*2);
    float* o = g_ans64b + n*64 + lane*2;
    o[0] = fmaxf(c.x + a0 + xr.x, 0.f);   // residual
    o[1] = fmaxf(c.y + a1 + xr.y, 0.f);
}

__global__ void k_postD(const float* __restrict__ fc3, float* __restrict__ out) {
    int n = blockIdx.x * blockDim.x + threadIdx.x;
    if (n >= NF) return;
    const float* x = g_ans64b + n*64;
    float a0 = 0.f, a1 = 0.f;
    #pragma unroll 8
    for (int cin = 0; cin < 64; cin++) {
        float xv = x[cin];
        float2 f = __ldg(reinterpret_cast<const float2*>(fc3 + cin*2));
        a0 = fmaf(xv, f.x, a0); a1 = fmaf(xv, f.y, a1);
    }
    out[n*2]     = g_acc2[n*2]     + a0;
    out[n*2 + 1] = g_acc2[n*2 + 1] + a1;
}

// ---------------- launch ----------------
extern "C" void kernel_launch(void* const* d_in, const int* in_sizes, int n_in,
                              void* d_out, int out_size) {
    (void)in_sizes; (void)n_in; (void)out_size;
    const float* fp    = (const float*)d_in[0];
    const float* bp    = (const float*)d_in[1];
    const float* ff    = (const float*)d_in[2];
    const float* bfeat = (const float*)d_in[3];
    const float* supp  = (const float*)d_in[4];
    const int*   fi    = (const int*)d_in[5];
    const int*   fj    = (const int*)d_in[6];
    const int*   bf    = (const int*)d_in[7];
    const int*   bb    = (const int*)d_in[8];
    const float* W0    = (const float*)d_in[9];
    const float* W1    = (const float*)d_in[10];
    const float* W2    = (const float*)d_in[11];
    const float* W3    = (const float*)d_in[12];
    const float* W4    = (const float*)d_in[13];
    const float* fc0   = (const float*)d_in[14];
    const float* fc1   = (const float*)d_in[15];
    const float* fc2   = (const float*)d_in[16];
    const float* fc3   = (const float*)d_in[17];
    float* out = (float*)d_out;

    k_init<<<1024, 256>>>();
    k_prep_fluid<<<EF/256, 256>>>(fp, fi, fj, supp);
    k_prep_bdy<<<EB/256, 256>>>(fp, bp, bf, bb, supp);
    k_scan<<<1, 32>>>();
    k_fill<<<EF/256, 256>>>();

    k_lin<<<NF/256, 256>>>(ff, fc0);
    k_conv_small<<<EF/256, 256>>>(ff,    W0, fi, fj, EF, 32, 0);
    k_conv_small<<<EB/256, 256>>>(bfeat, W1, bf, bb, EB, 64, 1);
    k_relu96<<<(NF*64)/256, 256>>>();

    k_conv_big<96><<<NTILES/8, 256>>>(W2, fi, fj);
    k_postB<<<NF/8, 256>>>(fc1);

    k_conv_big<64><<<NTILES/8, 256>>>(W3, fi, fj);
    k_postC<<<NF/8, 256>>>(fc2);

    k_conv_w4<<<EF/256, 256>>>(W4, fi, fj);
    k_postD<<<NF/256, 256>>>(fc3, out);
}

// round 4
// speedup vs baseline: 1.5425x; 1.5425x over previous
#include <cuda_runtime.h>
#include <stdint.h>

typedef unsigned long long ull;

#define NF 16384
#define NB 4096
#define EF 262144
#define EB 65536
#define EFPAD (EF + 64*8)      // 262656
#define EBPAD (EB + 64*8)      // 66048
#define NTILES_F (EFPAD/8)     // 32832
#define NTILES_B (EBPAD/8)     // 8256
#define FULL 0xffffffffu

// ---------------- scratch ----------------
__device__ __align__(16) float g_ans96 [NF*96];
__device__ __align__(16) float g_ans64a[NF*64];
__device__ __align__(16) float g_ans64b[NF*64];
__device__ __align__(16) float g_acc64a[NF*64];
__device__ __align__(16) float g_acc64b[NF*64];
__device__ __align__(16) float g_acc2  [NF*2];
__device__ __align__(16) float g_W2dup[64*96*128];   // [cell][cin][2*cout] duplicated
__device__ __align__(16) float g_W3dup[64*64*128];
__device__ __align__(16) float4 g_few[EF];
__device__ int   g_febkt[EF];
__device__ __align__(16) float4 g_bew[EB];
__device__ int   g_bbkt[EB];
__device__ int   g_bcnt[64],  g_boff[65],  g_bcur[64];
__device__ int   g_bcntB[64], g_boffB[65], g_bcurB[64];
__device__ int   g_blist[EFPAD];
__device__ int   g_blistB[EBPAD];
__device__ int   g_tilebkt[NTILES_F];
__device__ int   g_tilebktB[NTILES_B];

// ---------------- helpers ----------------
#define FMA2(d,a,b) asm("fma.rn.f32x2 %0, %1, %2, %0;" : "+l"(d) : "l"(a), "l"(b))

__device__ __forceinline__ float2 up2(ull u) {
    float2 f;
    asm("mov.b64 {%0, %1}, %2;" : "=f"(f.x), "=f"(f.y) : "l"(u));
    return f;
}

__device__ __forceinline__ void red2(float* p, float a, float b) {
    asm volatile("red.global.v2.f32.add [%0], {%1, %2};"
                 :: "l"(__cvta_generic_to_global(p)), "f"(a), "f"(b) : "memory");
}

__device__ __forceinline__ void edge_basis(float dx, float dy, int* bkt, float4* w) {
    float r  = sqrtf(dx*dx + dy*dy + 1e-12f);
    float u  = 2.f*r - 1.f;
    float v  = atan2f(dy, dx) * 0.3183098861837907f;
    float tu = (u + 1.f) * 3.5f;
    float tv = (v + 1.f) * 3.5f;
    int iu = (int)floorf(tu); iu = max(0, min(7, iu));
    int iv = (int)floorf(tv); iv = max(0, min(7, iv));
    float wu0 = fmaxf(0.f, 1.f - fabsf(tu - (float)iu));
    float wu1 = (iu < 7) ? fmaxf(0.f, 1.f - fabsf(tu - (float)(iu+1))) : 0.f;
    float wv0 = fmaxf(0.f, 1.f - fabsf(tv - (float)iv));
    float wv1 = (iv < 7) ? fmaxf(0.f, 1.f - fabsf(tv - (float)(iv+1))) : 0.f;
    *bkt = iu*8 + iv;
    *w = make_float4(wu0*wv0, wu0*wv1, wu1*wv0, wu1*wv1);
}

__device__ __forceinline__ void cells_of(int bkt, int* cellIdx) {
    int iu = bkt >> 3, iv = bkt & 7;
    int iu1 = min(iu+1, 7), iv1 = min(iv+1, 7);
    cellIdx[0] = iu*8+iv; cellIdx[1] = iu*8+iv1;
    cellIdx[2] = iu1*8+iv; cellIdx[3] = iu1*8+iv1;
}

// ---------------- zero bucket counters ----------------
__global__ void k_z() {
    int t = threadIdx.x;
    if (t < 64) { g_bcnt[t] = 0; g_bcntB[t] = 0; }
}

// ---------------- fused init + prep + Wdup + lin ----------------
__global__ void k_pre(const float* __restrict__ fp, const float* __restrict__ bp,
                      const float* __restrict__ ff, const float* __restrict__ bfeat,
                      const float* __restrict__ supp,
                      const int* __restrict__ fi, const int* __restrict__ fj,
                      const int* __restrict__ bfi, const int* __restrict__ bbi,
                      const float* __restrict__ W2, const float* __restrict__ W3,
                      const float* __restrict__ fc0) {
    int gt = blockIdx.x * blockDim.x + threadIdx.x;
    int gs = gridDim.x * blockDim.x;
    for (int i = gt; i < NF*64; i += gs) {
        int n = i >> 6, c = i & 63;
        g_ans96[n*96 + 32 + c] = 0.f;   // cols 0..31 fully overwritten by lin
        g_acc64a[i] = 0.f; g_acc64b[i] = 0.f;
    }
    for (int i = gt; i < NF*2;  i += gs) g_acc2[i] = 0.f;
    for (int i = gt; i < EFPAD; i += gs) g_blist[i]  = -1;
    for (int i = gt; i < EBPAD; i += gs) g_blistB[i] = -1;
    for (int i = gt; i < 64*96*64; i += gs) {
        float w = __ldg(W2 + i);
        ((float2*)g_W2dup)[i] = make_float2(w, w);   // i = (cell*96+cin)*64+co
    }
    for (int i = gt; i < 64*64*64; i += gs) {
        float w = __ldg(W3 + i);
        ((float2*)g_W3dup)[i] = make_float2(w, w);
    }
    float s = __ldg(supp);
    for (int e = gt; e < EF; e += gs) {
        int a = fi[e], b = fj[e];
        float dx = -(fp[b*2+0] - fp[a*2+0]) / s;
        float dy = -(fp[b*2+1] - fp[a*2+1]) / s;
        dx = fminf(1.f, fmaxf(-1.f, dx)); dy = fminf(1.f, fmaxf(-1.f, dy));
        int bkt; float4 w;
        edge_basis(dx, dy, &bkt, &w);
        g_few[e] = w; g_febkt[e] = bkt;
        atomicAdd(&g_bcnt[bkt], 1);
    }
    for (int e = gt; e < EB; e += gs) {
        int a = bfi[e], b = bbi[e];
        float dx = (bp[b*2+0] - fp[a*2+0]) / s;
        float dy = (bp[b*2+1] - fp[a*2+1]) / s;
        dx = fminf(1.f, fmaxf(-1.f, dx)); dy = fminf(1.f, fmaxf(-1.f, dy));
        int bkt; float4 w;
        edge_basis(dx, dy, &bkt, &w);
        g_bew[e] = w; g_bbkt[e] = bkt;
        atomicAdd(&g_bcntB[bkt], 1);
    }
    for (int n = gt; n < NF; n += gs) {
        float4 x = *reinterpret_cast<const float4*>(ff + n*4);
        float* o = g_ans96 + n*96;
        #pragma unroll
        for (int co = 0; co < 32; co++) {
            float a = x.x*__ldg(fc0+co) + x.y*__ldg(fc0+32+co)
                    + x.z*__ldg(fc0+64+co) + x.w*__ldg(fc0+96+co);
            o[co] = fmaxf(a, 0.f);
        }
    }
}

// ---------------- scan (padded to 8) + per-tile bucket ids ----------------
__global__ void k_scan() {
    __shared__ int sF[65], sB[65];
    if (threadIdx.x == 0) {
        int off = 0;
        for (int b = 0; b < 64; b++) {
            g_boff[b] = off; g_bcur[b] = off; sF[b] = off;
            off += (g_bcnt[b] + 7) & ~7;
        }
        g_boff[64] = off; sF[64] = off;
    }
    if (threadIdx.x == 32) {
        int off = 0;
        for (int b = 0; b < 64; b++) {
            g_boffB[b] = off; g_bcurB[b] = off; sB[b] = off;
            off += (g_bcntB[b] + 7) & ~7;
        }
        g_boffB[64] = off; sB[64] = off;
    }
    __syncthreads();
    for (int t = threadIdx.x; t < NTILES_F; t += blockDim.x) {
        int s = t*8; int b = 0;
        while (b < 63 && sF[b+1] <= s) b++;
        g_tilebkt[t] = (s < sF[64]) ? b : 0;
    }
    for (int t = threadIdx.x; t < NTILES_B; t += blockDim.x) {
        int s = t*8; int b = 0;
        while (b < 63 && sB[b+1] <= s) b++;
        g_tilebktB[t] = (s < sB[64]) ? b : 0;
    }
}

__global__ void k_fill() {
    int i = blockIdx.x * blockDim.x + threadIdx.x;
    if (i < EF) {
        int b = g_febkt[i];
        int pos = atomicAdd(&g_bcur[b], 1);
        g_blist[pos] = i;
    } else if (i < EF + EB) {
        int e = i - EF;
        int b = g_bbkt[e];
        int pos = atomicAdd(&g_bcurB[b], 1);
        g_blistB[pos] = e;
    }
}

// ---------------- small convs (cin=4, cout=32): bucketed tiles, lane=cout ----------------
__global__ void __launch_bounds__(256) k_front(const float* __restrict__ x,
        const float* __restrict__ W, const int* __restrict__ tgt,
        const int* __restrict__ src, int isB, int dstOff) {
    const int* blist    = isB ? g_blistB   : g_blist;
    const int* tb       = isB ? g_tilebktB : g_tilebkt;
    const float4* few   = isB ? g_bew      : g_few;
    __shared__ __align__(16) float4 xf[8][8];
    __shared__ float ws[8][4][8];
    int warp = threadIdx.x >> 5, lane = threadIdx.x & 31;
    int tile = blockIdx.x * 8 + warp;

    int eid = -1, srcv = -1, tgtv = -1; bool valid = false;
    if (lane < 8) {
        eid = blist[tile*8 + lane];
        valid = eid >= 0;
        if (valid) { srcv = src[eid]; tgtv = tgt[eid]; }
        float4 w = valid ? few[eid] : make_float4(0.f,0.f,0.f,0.f);
        ws[warp][0][lane] = w.x; ws[warp][1][lane] = w.y;
        ws[warp][2][lane] = w.z; ws[warp][3][lane] = w.w;
        xf[warp][lane] = valid ? *reinterpret_cast<const float4*>(x + srcv*4)
                               : make_float4(0.f,0.f,0.f,0.f);
    }
    __syncwarp();
    if (__ballot_sync(FULL, valid) == 0) return;
    int cellIdx[4]; cells_of(tb[tile], cellIdx);

    float acc[8];
    #pragma unroll
    for (int e = 0; e < 8; e++) acc[e] = 0.f;
    #pragma unroll
    for (int c = 0; c < 4; c++) {
        const float* Wc = W + cellIdx[c]*128;    // [cin=4][cout=32]
        float w0 = __ldg(Wc + lane),      w1 = __ldg(Wc + 32 + lane);
        float w2 = __ldg(Wc + 64 + lane), w3 = __ldg(Wc + 96 + lane);
        #pragma unroll
        for (int e = 0; e < 8; e++) {
            float4 xv = xf[warp][e];
            float s = fmaf(xv.x, w0, fmaf(xv.y, w1, fmaf(xv.z, w2, xv.w*w3)));
            acc[e] = fmaf(ws[warp][c][e], s, acc[e]);
        }
    }
    #pragma unroll
    for (int e = 0; e < 8; e++) {
        int t = __shfl_sync(FULL, tgtv, e);
        if (t >= 0) atomicAdd(g_ans96 + t*96 + dstOff + lane, acc[e]);
    }
}

// ---------------- big convs (cout=64): FFMA2 edge-pair packing ----------------
template<int CIN, bool RELU>
__global__ void __launch_bounds__(256) k_big(const int* __restrict__ fi,
                                             const int* __restrict__ fj) {
    const float* x  = (CIN == 96) ? g_ans96  : g_ans64a;
    const float* Wd = (CIN == 96) ? g_W2dup  : g_W3dup;
    float* out      = (CIN == 96) ? g_acc64a : g_acc64b;

    __shared__ __align__(16) float xs[8][CIN*8];
    __shared__ __align__(16) float ws[8][4][8];
    int warp = threadIdx.x >> 5, lane = threadIdx.x & 31;
    int tile = blockIdx.x * 8 + warp;

    int eid = -1, srcv = -1, tgtv = -1; bool valid = false;
    if (lane < 8) {
        eid = g_blist[tile*8 + lane];
        valid = eid >= 0;
        if (valid) { srcv = fj[eid]; tgtv = fi[eid]; }
        float4 w = valid ? g_few[eid] : make_float4(0.f,0.f,0.f,0.f);
        ws[warp][0][lane] = w.x; ws[warp][1][lane] = w.y;
        ws[warp][2][lane] = w.z; ws[warp][3][lane] = w.w;
    }
    if (__ballot_sync(FULL, valid) == 0) return;

    // gather x rows coalesced, transpose into xs[cin][e]
    #pragma unroll
    for (int e = 0; e < 8; e++) {
        int s = __shfl_sync(FULL, srcv, e);
        #pragma unroll
        for (int k = 0; k < CIN/32; k++) {
            float v = 0.f;
            if (s >= 0) {
                v = __ldg(x + s*CIN + k*32 + lane);
                if (RELU) v = fmaxf(v, 0.f);
            }
            xs[warp][(k*32 + lane)*8 + e] = v;
        }
    }
    __syncwarp();

    int cellIdx[4]; cells_of(g_tilebkt[tile], cellIdx);

    ull acc[4][2];
    #pragma unroll
    for (int p = 0; p < 4; p++) { acc[p][0] = 0ull; acc[p][1] = 0ull; }

    const ulonglong2* xp = reinterpret_cast<const ulonglong2*>(xs[warp]);
    #pragma unroll
    for (int c = 0; c < 4; c++) {
        const ulonglong2* Wc = reinterpret_cast<const ulonglong2*>(Wd)
                             + (size_t)cellIdx[c]*(CIN*32) + lane;
        ull tmp[4][2];
        #pragma unroll
        for (int p = 0; p < 4; p++) { tmp[p][0] = 0ull; tmp[p][1] = 0ull; }
        #pragma unroll 4
        for (int cin = 0; cin < CIN; cin++) {
            ulonglong2 wd = __ldg(Wc + cin*32);   // {w0,w0},{w1,w1}
            ulonglong2 xA = xp[cin*2];            // {x0,x1},{x2,x3}
            ulonglong2 xB = xp[cin*2 + 1];        // {x4,x5},{x6,x7}
            FMA2(tmp[0][0], xA.x, wd.x); FMA2(tmp[0][1], xA.x, wd.y);
            FMA2(tmp[1][0], xA.y, wd.x); FMA2(tmp[1][1], xA.y, wd.y);
            FMA2(tmp[2][0], xB.x, wd.x); FMA2(tmp[2][1], xB.x, wd.y);
            FMA2(tmp[3][0], xB.y, wd.x); FMA2(tmp[3][1], xB.y, wd.y);
        }
        const ull* wsp = reinterpret_cast<const ull*>(ws[warp][c]);
        #pragma unroll
        for (int p = 0; p < 4; p++) {
            ull wp = wsp[p];
            FMA2(acc[p][0], wp, tmp[p][0]);
            FMA2(acc[p][1], wp, tmp[p][1]);
        }
    }
    #pragma unroll
    for (int e = 0; e < 8; e++) {
        int t = __shfl_sync(FULL, tgtv, e);
        if (t >= 0) {
            int p = e >> 1, h = e & 1;
            float2 a = up2(acc[p][0]);
            float2 b = up2(acc[p][1]);
            red2(out + t*64 + lane*2, h ? a.y : a.x, h ? b.y : b.x);
        }
    }
}

// ---------------- W4 conv (cin=64, cout=2): bucketed, lane=(cell,edge) ----------------
__global__ void __launch_bounds__(256) k_w4(const float* __restrict__ W4,
        const int* __restrict__ fi, const int* __restrict__ fj) {
    __shared__ float xs[8][8][65];
    __shared__ float ws[8][4][8];
    int warp = threadIdx.x >> 5, lane = threadIdx.x & 31;
    int tile = blockIdx.x * 8 + warp;

    int eid = -1, srcv = -1, tgtv = -1; bool valid = false;
    if (lane < 8) {
        eid = g_blist[tile*8 + lane];
        valid = eid >= 0;
        if (valid) { srcv = fj[eid]; tgtv = fi[eid]; }
        float4 w = valid ? g_few[eid] : make_float4(0.f,0.f,0.f,0.f);
        ws[warp][0][lane] = w.x; ws[warp][1][lane] = w.y;
        ws[warp][2][lane] = w.z; ws[warp][3][lane] = w.w;
    }
    if (__ballot_sync(FULL, valid) == 0) return;
    #pragma unroll
    for (int e = 0; e < 8; e++) {
        int s = __shfl_sync(FULL, srcv, e);
        #pragma unroll
        for (int k = 0; k < 2; k++)
            xs[warp][e][k*32 + lane] = (s >= 0) ? __ldg(g_ans64b + s*64 + k*32 + lane) : 0.f;
    }
    __syncwarp();
    int cellIdx[4]; cells_of(g_tilebkt[tile], cellIdx);

    int c = lane >> 3, e = lane & 7;
    const float2* Wc = reinterpret_cast<const float2*>(W4) + cellIdx[c]*64;
    float t0 = 0.f, t1 = 0.f;
    #pragma unroll 8
    for (int cin = 0; cin < 64; cin++) {
        float xv = xs[warp][e][cin];
        float2 wv = __ldg(Wc + cin);
        t0 = fmaf(xv, wv.x, t0); t1 = fmaf(xv, wv.y, t1);
    }
    float wc = ws[warp][c][e];
    t0 *= wc; t1 *= wc;
    t0 += __shfl_xor_sync(FULL, t0, 8);  t1 += __shfl_xor_sync(FULL, t1, 8);
    t0 += __shfl_xor_sync(FULL, t0, 16); t1 += __shfl_xor_sync(FULL, t1, 16);
    if (lane < 8 && tgtv >= 0) red2(g_acc2 + tgtv*2, t0, t1);
}

// ---------------- dense epilogues ----------------
__global__ void k_postB(const float* __restrict__ fc1) {
    int warp = threadIdx.x >> 5, lane = threadIdx.x & 31;
    int n = blockIdx.x * 8 + warp;
    const float* xrow = g_ans96 + n*96;
    float a0 = 0.f, a1 = 0.f;
    #pragma unroll
    for (int k = 0; k < 96; k += 32) {
        float xv = fmaxf(xrow[k + lane], 0.f);   // relu-at-read (cols 32..95 pre-relu)
        #pragma unroll
        for (int j = 0; j < 32; j++) {
            float xj = __shfl_sync(FULL, xv, j);
            float2 f = __ldg(reinterpret_cast<const float2*>(fc1 + (k+j)*64 + lane*2));
            a0 = fmaf(xj, f.x, a0); a1 = fmaf(xj, f.y, a1);
        }
    }
    float2 c = *reinterpret_cast<const float2*>(g_acc64a + n*64 + lane*2);
    float* o = g_ans64a + n*64 + lane*2;
    o[0] = fmaxf(c.x + a0, 0.f);
    o[1] = fmaxf(c.y + a1, 0.f);
}

__global__ void k_postC(const float* __restrict__ fc2) {
    int warp = threadIdx.x >> 5, lane = threadIdx.x & 31;
    int n = blockIdx.x * 8 + warp;
    const float* xrow = g_ans64a + n*64;
    float a0 = 0.f, a1 = 0.f;
    #pragma unroll
    for (int k = 0; k < 64; k += 32) {
        float xv = xrow[k + lane];
        #pragma unroll
        for (int j = 0; j < 32; j++) {
            float xj = __shfl_sync(FULL, xv, j);
            float2 f = __ldg(reinterpret_cast<const float2*>(fc2 + (k+j)*64 + lane*2));
            a0 = fmaf(xj, f.x, a0); a1 = fmaf(xj, f.y, a1);
        }
    }
    float2 c  = *reinterpret_cast<const float2*>(g_acc64b + n*64 + lane*2);
    float2 xr = *reinterpret_cast<const float2*>(g_ans64a + n*64 + lane*2);
    float* o = g_ans64b + n*64 + lane*2;
    o[0] = fmaxf(c.x + a0 + xr.x, 0.f);
    o[1] = fmaxf(c.y + a1 + xr.y, 0.f);
}

__global__ void k_postD(const float* __restrict__ fc3, float* __restrict__ out) {
    int n = blockIdx.x * blockDim.x + threadIdx.x;
    if (n >= NF) return;
    const float* x = g_ans64b + n*64;
    float a0 = 0.f, a1 = 0.f;
    #pragma unroll 8
    for (int cin = 0; cin < 64; cin++) {
        float xv = x[cin];
        float2 f = __ldg(reinterpret_cast<const float2*>(fc3 + cin*2));
        a0 = fmaf(xv, f.x, a0); a1 = fmaf(xv, f.y, a1);
    }
    out[n*2]     = g_acc2[n*2]     + a0;
    out[n*2 + 1] = g_acc2[n*2 + 1] + a1;
}

// ---------------- launch ----------------
extern "C" void kernel_launch(void* const* d_in, const int* in_sizes, int n_in,
                              void* d_out, int out_size) {
    (void)in_sizes; (void)n_in; (void)out_size;
    const float* fp    = (const float*)d_in[0];
    const float* bp    = (const float*)d_in[1];
    const float* ff    = (const float*)d_in[2];
    const float* bfeat = (const float*)d_in[3];
    const float* supp  = (const float*)d_in[4];
    const int*   fi    = (const int*)d_in[5];
    const int*   fj    = (const int*)d_in[6];
    const int*   bf    = (const int*)d_in[7];
    const int*   bb    = (const int*)d_in[8];
    const float* W0    = (const float*)d_in[9];
    const float* W1    = (const float*)d_in[10];
    const float* W2    = (const float*)d_in[11];
    const float* W3    = (const float*)d_in[12];
    const float* W4    = (const float*)d_in[13];
    const float* fc0   = (const float*)d_in[14];
    const float* fc1   = (const float*)d_in[15];
    const float* fc2   = (const float*)d_in[16];
    const float* fc3   = (const float*)d_in[17];
    float* out = (float*)d_out;

    k_z<<<1, 128>>>();
    k_pre<<<1024, 256>>>(fp, bp, ff, bfeat, supp, fi, fj, bf, bb, W2, W3, fc0);
    k_scan<<<1, 256>>>();
    k_fill<<<(EF + EB)/256, 256>>>();

    k_front<<<NTILES_F/8, 256>>>(ff,    W0, fi, fj, 0, 32);
    k_front<<<NTILES_B/8, 256>>>(bfeat, W1, bf, bb, 1, 64);

    k_big<96, true ><<<NTILES_F/8, 256>>>(fi, fj);
    k_postB<<<NF/8, 256>>>(fc1);

    k_big<64, false><<<NTILES_F/8, 256>>>(fi, fj);
    k_postC<<<NF/8, 256>>>(fc2);

    k_w4<<<NTILES_F/8, 256>>>(W4, fi, fj);
    k_postD<<<NF/256, 256>>>(fc3, out);
}

// round 6
// speedup vs baseline: 1.7075x; 1.1069x over previous
#include <cuda_runtime.h>
#include <stdint.h>

typedef unsigned long long ull;

#define NF 16384
#define NB 4096
#define EF 262144
#define EB 65536
#define EFPAD (EF + 64*8)      // 262656
#define EBPAD (EB + 64*8)      // 66048
#define NTILES_F (EFPAD/8)     // 32832
#define NTILES_B (EBPAD/8)     // 8256
#define FULL 0xffffffffu
#define NBLK_F (EF/1024)       // 256
#define NBLK_B (EB/1024)       // 64

// ---------------- scratch ----------------
__device__ __align__(16) float g_ans96 [NF*96];
__device__ __align__(16) float g_ans64a[NF*64];
__device__ __align__(16) float g_ans64b[NF*64];
__device__ __align__(16) float g_acc64a[NF*64];
__device__ __align__(16) float g_acc64b[NF*64];
__device__ __align__(16) float g_acc2  [NF*2];
__device__ __align__(16) float g_W2dup[64*96*128];   // [cell][cin][2*cout] duplicated
__device__ __align__(16) float g_W3dup[64*64*128];
__device__ __align__(16) float4 g_few[EF];
__device__ int   g_febkt[EF];
__device__ __align__(16) float4 g_bew[EB];
__device__ int   g_bbkt[EB];
__device__ int   g_bcnt[64],  g_boff[65],  g_bcur[64];
__device__ int   g_bcntB[64], g_boffB[65], g_bcurB[64];
__device__ int   g_blist[EFPAD];
__device__ int   g_blistB[EBPAD];
__device__ int   g_tilebkt[NTILES_F];
__device__ int   g_tilebktB[NTILES_B];

// ---------------- helpers ----------------
#define FMA2(d,a,b) asm("fma.rn.f32x2 %0, %1, %2, %0;" : "+l"(d) : "l"(a), "l"(b))

__device__ __forceinline__ float2 up2(ull u) {
    float2 f;
    asm("mov.b64 {%0, %1}, %2;" : "=f"(f.x), "=f"(f.y) : "l"(u));
    return f;
}

__device__ __forceinline__ void red2(float* p, float a, float b) {
    asm volatile("red.global.v2.f32.add [%0], {%1, %2};"
                 :: "l"(__cvta_generic_to_global(p)), "f"(a), "f"(b) : "memory");
}

__device__ __forceinline__ void edge_basis(float dx, float dy, int* bkt, float4* w) {
    float r  = sqrtf(dx*dx + dy*dy + 1e-12f);
    float u  = 2.f*r - 1.f;
    float v  = atan2f(dy, dx) * 0.3183098861837907f;
    float tu = (u + 1.f) * 3.5f;
    float tv = (v + 1.f) * 3.5f;
    int iu = (int)floorf(tu); iu = max(0, min(7, iu));
    int iv = (int)floorf(tv); iv = max(0, min(7, iv));
    float wu0 = fmaxf(0.f, 1.f - fabsf(tu - (float)iu));
    float wu1 = (iu < 7) ? fmaxf(0.f, 1.f - fabsf(tu - (float)(iu+1))) : 0.f;
    float wv0 = fmaxf(0.f, 1.f - fabsf(tv - (float)iv));
    float wv1 = (iv < 7) ? fmaxf(0.f, 1.f - fabsf(tv - (float)(iv+1))) : 0.f;
    *bkt = iu*8 + iv;
    *w = make_float4(wu0*wv0, wu0*wv1, wu1*wv0, wu1*wv1);
}

__device__ __forceinline__ void cells_of(int bkt, int* cellIdx) {
    int iu = bkt >> 3, iv = bkt & 7;
    int iu1 = min(iu+1, 7), iv1 = min(iv+1, 7);
    cellIdx[0] = iu*8+iv; cellIdx[1] = iu*8+iv1;
    cellIdx[2] = iu1*8+iv; cellIdx[3] = iu1*8+iv1;
}

// ---------------- zero bucket counters ----------------
__global__ void k_z() {
    int t = threadIdx.x;
    if (t < 64) { g_bcnt[t] = 0; g_bcntB[t] = 0; }
}

// ---------------- init + Wdup + lin (no atomics) ----------------
__global__ void k_pre(const float* __restrict__ ff,
                      const float* __restrict__ W2, const float* __restrict__ W3,
                      const float* __restrict__ fc0) {
    int gt = blockIdx.x * blockDim.x + threadIdx.x;
    int gs = gridDim.x * blockDim.x;
    for (int i = gt; i < NF*64; i += gs) {
        int n = i >> 6, c = i & 63;
        g_ans96[n*96 + 32 + c] = 0.f;   // cols 0..31 fully overwritten by lin
        g_acc64a[i] = 0.f; g_acc64b[i] = 0.f;
    }
    for (int i = gt; i < NF*2;  i += gs) g_acc2[i] = 0.f;
    for (int i = gt; i < EFPAD; i += gs) g_blist[i]  = -1;
    for (int i = gt; i < EBPAD; i += gs) g_blistB[i] = -1;
    for (int i = gt; i < 64*96*64; i += gs) {
        float w = __ldg(W2 + i);
        ((float2*)g_W2dup)[i] = make_float2(w, w);
    }
    for (int i = gt; i < 64*64*64; i += gs) {
        float w = __ldg(W3 + i);
        ((float2*)g_W3dup)[i] = make_float2(w, w);
    }
    for (int n = gt; n < NF; n += gs) {
        float4 x = *reinterpret_cast<const float4*>(ff + n*4);
        float* o = g_ans96 + n*96;
        #pragma unroll
        for (int co = 0; co < 32; co++) {
            float a = x.x*__ldg(fc0+co) + x.y*__ldg(fc0+32+co)
                    + x.z*__ldg(fc0+64+co) + x.w*__ldg(fc0+96+co);
            o[co] = fmaxf(a, 0.f);
        }
    }
}

// ---------------- edge basis + block-aggregated histogram ----------------
__global__ void __launch_bounds__(256) k_count(const float* __restrict__ fp,
        const float* __restrict__ bp, const float* __restrict__ supp,
        const int* __restrict__ fi, const int* __restrict__ fj,
        const int* __restrict__ bfi, const int* __restrict__ bbi) {
    __shared__ int h[64];
    int tid = threadIdx.x;
    if (tid < 64) h[tid] = 0;
    __syncthreads();
    float s = __ldg(supp);
    bool isB = blockIdx.x >= NBLK_F;
    if (!isB) {
        int base = blockIdx.x * 1024;
        #pragma unroll
        for (int k = 0; k < 4; k++) {
            int e = base + k*256 + tid;
            int a = fi[e], b = fj[e];
            float dx = -(fp[b*2+0] - fp[a*2+0]) / s;
            float dy = -(fp[b*2+1] - fp[a*2+1]) / s;
            dx = fminf(1.f, fmaxf(-1.f, dx)); dy = fminf(1.f, fmaxf(-1.f, dy));
            int bkt; float4 w;
            edge_basis(dx, dy, &bkt, &w);
            g_few[e] = w; g_febkt[e] = bkt;
            atomicAdd(&h[bkt], 1);
        }
        __syncthreads();
        if (tid < 64 && h[tid]) atomicAdd(&g_bcnt[tid], h[tid]);
    } else {
        int base = (blockIdx.x - NBLK_F) * 1024;
        #pragma unroll
        for (int k = 0; k < 4; k++) {
            int e = base + k*256 + tid;
            int a = bfi[e], b = bbi[e];
            float dx = (bp[b*2+0] - fp[a*2+0]) / s;
            float dy = (bp[b*2+1] - fp[a*2+1]) / s;
            dx = fminf(1.f, fmaxf(-1.f, dx)); dy = fminf(1.f, fmaxf(-1.f, dy));
            int bkt; float4 w;
            edge_basis(dx, dy, &bkt, &w);
            g_bew[e] = w; g_bbkt[e] = bkt;
            atomicAdd(&h[bkt], 1);
        }
        __syncthreads();
        if (tid < 64 && h[tid]) atomicAdd(&g_bcntB[tid], h[tid]);
    }
}

// ---------------- scan (padded to 8) + per-tile bucket ids ----------------
__global__ void k_scan() {
    __shared__ int sF[65], sB[65];
    if (threadIdx.x == 0) {
        int off = 0;
        for (int b = 0; b < 64; b++) {
            g_boff[b] = off; g_bcur[b] = off; sF[b] = off;
            off += (g_bcnt[b] + 7) & ~7;
        }
        g_boff[64] = off; sF[64] = off;
    }
    if (threadIdx.x == 32) {
        int off = 0;
        for (int b = 0; b < 64; b++) {
            g_boffB[b] = off; g_bcurB[b] = off; sB[b] = off;
            off += (g_bcntB[b] + 7) & ~7;
        }
        g_boffB[64] = off; sB[64] = off;
    }
    __syncthreads();
    for (int t = threadIdx.x; t < NTILES_F; t += blockDim.x) {
        int s = t*8; int b = 0;
        while (b < 63 && sF[b+1] <= s) b++;
        g_tilebkt[t] = (s < sF[64]) ? b : 0;
    }
    for (int t = threadIdx.x; t < NTILES_B; t += blockDim.x) {
        int s = t*8; int b = 0;
        while (b < 63 && sB[b+1] <= s) b++;
        g_tilebktB[t] = (s < sB[64]) ? b : 0;
    }
}

// ---------------- block-aggregated fill ----------------
__global__ void __launch_bounds__(256) k_fillA() {
    __shared__ int h[64], base[64];
    int tid = threadIdx.x;
    if (tid < 64) h[tid] = 0;
    __syncthreads();
    bool isB = blockIdx.x >= NBLK_F;
    const int* bktArr = isB ? g_bbkt  : g_febkt;
    int* cur          = isB ? g_bcurB : g_bcur;
    int* list         = isB ? g_blistB : g_blist;
    int eb = (isB ? (blockIdx.x - NBLK_F) : blockIdx.x) * 1024;
    int myb[4];
    #pragma unroll
    for (int k = 0; k < 4; k++) {
        myb[k] = bktArr[eb + k*256 + tid];
        atomicAdd(&h[myb[k]], 1);
    }
    __syncthreads();
    if (tid < 64) {
        base[tid] = h[tid] ? atomicAdd(&cur[tid], h[tid]) : 0;
        h[tid] = 0;
    }
    __syncthreads();
    #pragma unroll
    for (int k = 0; k < 4; k++) {
        int p = base[myb[k]] + atomicAdd(&h[myb[k]], 1);
        list[p] = eb + k*256 + tid;
    }
}

// ---------------- small convs (cin=4, cout=32): bucketed tiles, lane=cout ----------------
__global__ void __launch_bounds__(256) k_front(const float* __restrict__ x,
        const float* __restrict__ W, const int* __restrict__ tgt,
        const int* __restrict__ src, int isB, int dstOff) {
    const int* blist    = isB ? g_blistB   : g_blist;
    const int* tb       = isB ? g_tilebktB : g_tilebkt;
    const float4* few   = isB ? g_bew      : g_few;
    __shared__ __align__(16) float4 xf[8][8];
    __shared__ float ws[8][4][8];
    int warp = threadIdx.x >> 5, lane = threadIdx.x & 31;
    int tile = blockIdx.x * 8 + warp;

    int eid = -1, srcv = -1, tgtv = -1; bool valid = false;
    if (lane < 8) {
        eid = blist[tile*8 + lane];
        valid = eid >= 0;
        if (valid) { srcv = src[eid]; tgtv = tgt[eid]; }
        float4 w = valid ? few[eid] : make_float4(0.f,0.f,0.f,0.f);
        ws[warp][0][lane] = w.x; ws[warp][1][lane] = w.y;
        ws[warp][2][lane] = w.z; ws[warp][3][lane] = w.w;
        xf[warp][lane] = valid ? *reinterpret_cast<const float4*>(x + srcv*4)
                               : make_float4(0.f,0.f,0.f,0.f);
    }
    __syncwarp();
    if (__ballot_sync(FULL, valid) == 0) return;
    int cellIdx[4]; cells_of(tb[tile], cellIdx);

    float acc[8];
    #pragma unroll
    for (int e = 0; e < 8; e++) acc[e] = 0.f;
    #pragma unroll
    for (int c = 0; c < 4; c++) {
        const float* Wc = W + cellIdx[c]*128;    // [cin=4][cout=32]
        float w0 = __ldg(Wc + lane),      w1 = __ldg(Wc + 32 + lane);
        float w2 = __ldg(Wc + 64 + lane), w3 = __ldg(Wc + 96 + lane);
        #pragma unroll
        for (int e = 0; e < 8; e++) {
            float4 xv = xf[warp][e];
            float s = fmaf(xv.x, w0, fmaf(xv.y, w1, fmaf(xv.z, w2, xv.w*w3)));
            acc[e] = fmaf(ws[warp][c][e], s, acc[e]);
        }
    }
    #pragma unroll
    for (int e = 0; e < 8; e++) {
        float v  = acc[e];
        float nb = __shfl_down_sync(FULL, v, 1);
        int t = __shfl_sync(FULL, tgtv, e);
        if (t >= 0 && (lane & 1) == 0)
            red2(g_ans96 + t*96 + dstOff + lane, v, nb);
    }
}

// ---------------- big convs (cout=64): FFMA2 edge-pair packing ----------------
template<int CIN, bool RELU>
__global__ void __launch_bounds__(256) k_big(const int* __restrict__ fi,
                                             const int* __restrict__ fj) {
    const float* x  = (CIN == 96) ? g_ans96  : g_ans64a;
    const float* Wd = (CIN == 96) ? g_W2dup  : g_W3dup;
    float* out      = (CIN == 96) ? g_acc64a : g_acc64b;

    __shared__ __align__(16) float xs[8][CIN*8];
    __shared__ __align__(16) float ws[8][4][8];
    int warp = threadIdx.x >> 5, lane = threadIdx.x & 31;
    int tile = blockIdx.x * 8 + warp;

    int eid = -1, srcv = -1, tgtv = -1; bool valid = false;
    if (lane < 8) {
        eid = g_blist[tile*8 + lane];
        valid = eid >= 0;
        if (valid) { srcv = fj[eid]; tgtv = fi[eid]; }
        float4 w = valid ? g_few[eid] : make_float4(0.f,0.f,0.f,0.f);
        ws[warp][0][lane] = w.x; ws[warp][1][lane] = w.y;
        ws[warp][2][lane] = w.z; ws[warp][3][lane] = w.w;
    }
    if (__ballot_sync(FULL, valid) == 0) return;

    #pragma unroll
    for (int e = 0; e < 8; e++) {
        int s = __shfl_sync(FULL, srcv, e);
        #pragma unroll
        for (int k = 0; k < CIN/32; k++) {
            float v = 0.f;
            if (s >= 0) {
                v = __ldg(x + s*CIN + k*32 + lane);
                if (RELU) v = fmaxf(v, 0.f);
            }
            xs[warp][(k*32 + lane)*8 + e] = v;
        }
    }
    __syncwarp();

    int cellIdx[4]; cells_of(g_tilebkt[tile], cellIdx);

    ull acc[4][2];
    #pragma unroll
    for (int p = 0; p < 4; p++) { acc[p][0] = 0ull; acc[p][1] = 0ull; }

    const ulonglong2* xp = reinterpret_cast<const ulonglong2*>(xs[warp]);
    #pragma unroll
    for (int c = 0; c < 4; c++) {
        const ulonglong2* Wc = reinterpret_cast<const ulonglong2*>(Wd)
                             + (size_t)cellIdx[c]*(CIN*32) + lane;
        ull tmp[4][2];
        #pragma unroll
        for (int p = 0; p < 4; p++) { tmp[p][0] = 0ull; tmp[p][1] = 0ull; }
        #pragma unroll 4
        for (int cin = 0; cin < CIN; cin++) {
            ulonglong2 wd = __ldg(Wc + cin*32);
            ulonglong2 xA = xp[cin*2];
            ulonglong2 xB = xp[cin*2 + 1];
            FMA2(tmp[0][0], xA.x, wd.x); FMA2(tmp[0][1], xA.x, wd.y);
            FMA2(tmp[1][0], xA.y, wd.x); FMA2(tmp[1][1], xA.y, wd.y);
            FMA2(tmp[2][0], xB.x, wd.x); FMA2(tmp[2][1], xB.x, wd.y);
            FMA2(tmp[3][0], xB.y, wd.x); FMA2(tmp[3][1], xB.y, wd.y);
        }
        const ull* wsp = reinterpret_cast<const ull*>(ws[warp][c]);
        #pragma unroll
        for (int p = 0; p < 4; p++) {
            ull wp = wsp[p];
            FMA2(acc[p][0], wp, tmp[p][0]);
            FMA2(acc[p][1], wp, tmp[p][1]);
        }
    }
    #pragma unroll
    for (int e = 0; e < 8; e++) {
        int t = __shfl_sync(FULL, tgtv, e);
        if (t >= 0) {
            int p = e >> 1, h = e & 1;
            float2 a = up2(acc[p][0]);
            float2 b = up2(acc[p][1]);
            red2(out + t*64 + lane*2, h ? a.y : a.x, h ? b.y : b.x);
        }
    }
}

// ---------------- W4 conv (cin=64, cout=2): bucketed, lane=(cell,edge) ----------------
__global__ void __launch_bounds__(256) k_w4(const float* __restrict__ W4,
        const int* __restrict__ fi, const int* __restrict__ fj) {
    __shared__ float xs[8][8][65];
    __shared__ float ws[8][4][8];
    int warp = threadIdx.x >> 5, lane = threadIdx.x & 31;
    int tile = blockIdx.x * 8 + warp;

    int eid = -1, srcv = -1, tgtv = -1; bool valid = false;
    if (lane < 8) {
        eid = g_blist[tile*8 + lane];
        valid = eid >= 0;
        if (valid) { srcv = fj[eid]; tgtv = fi[eid]; }
        float4 w = valid ? g_few[eid] : make_float4(0.f,0.f,0.f,0.f);
        ws[warp][0][lane] = w.x; ws[warp][1][lane] = w.y;
        ws[warp][2][lane] = w.z; ws[warp][3][lane] = w.w;
    }
    if (__ballot_sync(FULL, valid) == 0) return;
    #pragma unroll
    for (int e = 0; e < 8; e++) {
        int s = __shfl_sync(FULL, srcv, e);
        #pragma unroll
        for (int k = 0; k < 2; k++)
            xs[warp][e][k*32 + lane] = (s >= 0) ? __ldg(g_ans64b + s*64 + k*32 + lane) : 0.f;
    }
    __syncwarp();
    int cellIdx[4]; cells_of(g_tilebkt[tile], cellIdx);

    int c = lane >> 3, e = lane & 7;
    const float2* Wc = reinterpret_cast<const float2*>(W4) + cellIdx[c]*64;
    float t0 = 0.f, t1 = 0.f;
    #pragma unroll 8
    for (int cin = 0; cin < 64; cin++) {
        float xv = xs[warp][e][cin];
        float2 wv = __ldg(Wc + cin);
        t0 = fmaf(xv, wv.x, t0); t1 = fmaf(xv, wv.y, t1);
    }
    float wc = ws[warp][c][e];
    t0 *= wc; t1 *= wc;
    t0 += __shfl_xor_sync(FULL, t0, 8);  t1 += __shfl_xor_sync(FULL, t1, 8);
    t0 += __shfl_xor_sync(FULL, t0, 16); t1 += __shfl_xor_sync(FULL, t1, 16);
    if (lane < 8 && tgtv >= 0) red2(g_acc2 + tgtv*2, t0, t1);
}

// ---------------- dense epilogues ----------------
__global__ void k_postB(const float* __restrict__ fc1) {
    int warp = threadIdx.x >> 5, lane = threadIdx.x & 31;
    int n = blockIdx.x * 8 + warp;
    const float* xrow = g_ans96 + n*96;
    float a0 = 0.f, a1 = 0.f;
    #pragma unroll
    for (int k = 0; k < 96; k += 32) {
        float xv = fmaxf(xrow[k + lane], 0.f);
        #pragma unroll
        for (int j = 0; j < 32; j++) {
            float xj = __shfl_sync(FULL, xv, j);
            float2 f = __ldg(reinterpret_cast<const float2*>(fc1 + (k+j)*64 + lane*2));
            a0 = fmaf(xj, f.x, a0); a1 = fmaf(xj, f.y, a1);
        }
    }
    float2 c = *reinterpret_cast<const float2*>(g_acc64a + n*64 + lane*2);
    float* o = g_ans64a + n*64 + lane*2;
    o[0] = fmaxf(c.x + a0, 0.f);
    o[1] = fmaxf(c.y + a1, 0.f);
}

__global__ void k_postC(const float* __restrict__ fc2) {
    int warp = threadIdx.x >> 5, lane = threadIdx.x & 31;
    int n = blockIdx.x * 8 + warp;
    const float* xrow = g_ans64a + n*64;
    float a0 = 0.f, a1 = 0.f;
    #pragma unroll
    for (int k = 0; k < 64; k += 32) {
        float xv = xrow[k + lane];
        #pragma unroll
        for (int j = 0; j < 32; j++) {
            float xj = __shfl_sync(FULL, xv, j);
            float2 f = __ldg(reinterpret_cast<const float2*>(fc2 + (k+j)*64 + lane*2));
            a0 = fmaf(xj, f.x, a0); a1 = fmaf(xj, f.y, a1);
        }
    }
    float2 c  = *reinterpret_cast<const float2*>(g_acc64b + n*64 + lane*2);
    float2 xr = *reinterpret_cast<const float2*>(g_ans64a + n*64 + lane*2);
    float* o = g_ans64b + n*64 + lane*2;
    o[0] = fmaxf(c.x + a0 + xr.x, 0.f);
    o[1] = fmaxf(c.y + a1 + xr.y, 0.f);
}

__global__ void k_postD(const float* __restrict__ fc3, float* __restrict__ out) {
    int n = blockIdx.x * blockDim.x + threadIdx.x;
    if (n >= NF) return;
    const float* x = g_ans64b + n*64;
    float a0 = 0.f, a1 = 0.f;
    #pragma unroll 8
    for (int cin = 0; cin < 64; cin++) {
        float xv = x[cin];
        float2 f = __ldg(reinterpret_cast<const float2*>(fc3 + cin*2));
        a0 = fmaf(xv, f.x, a0); a1 = fmaf(xv, f.y, a1);
    }
    out[n*2]     = g_acc2[n*2]     + a0;
    out[n*2 + 1] = g_acc2[n*2 + 1] + a1;
}

// ---------------- launch ----------------
extern "C" void kernel_launch(void* const* d_in, const int* in_sizes, int n_in,
                              void* d_out, int out_size) {
    (void)in_sizes; (void)n_in; (void)out_size;
    const float* fp    = (const float*)d_in[0];
    const float* bp    = (const float*)d_in[1];
    const float* ff    = (const float*)d_in[2];
    const float* bfeat = (const float*)d_in[3];
    const float* supp  = (const float*)d_in[4];
    const int*   fi    = (const int*)d_in[5];
    const int*   fj    = (const int*)d_in[6];
    const int*   bf    = (const int*)d_in[7];
    const int*   bb    = (const int*)d_in[8];
    const float* W0    = (const float*)d_in[9];
    const float* W1    = (const float*)d_in[10];
    const float* W2    = (const float*)d_in[11];
    const float* W3    = (const float*)d_in[12];
    const float* W4    = (const float*)d_in[13];
    const float* fc0   = (const float*)d_in[14];
    const float* fc1   = (const float*)d_in[15];
    const float* fc2   = (const float*)d_in[16];
    const float* fc3   = (const float*)d_in[17];
    float* out = (float*)d_out;

    k_z<<<1, 128>>>();
    k_pre<<<1024, 256>>>(ff, W2, W3, fc0);
    k_count<<<NBLK_F + NBLK_B, 256>>>(fp, bp, supp, fi, fj, bf, bb);
    k_scan<<<1, 256>>>();
    k_fillA<<<NBLK_F + NBLK_B, 256>>>();

    k_front<<<NTILES_F/8, 256>>>(ff,    W0, fi, fj, 0, 32);
    k_front<<<NTILES_B/8, 256>>>(bfeat, W1, bf, bb, 1, 64);

    k_big<96, true ><<<NTILES_F/8, 256>>>(fi, fj);
    k_postB<<<NF/8, 256>>>(fc1);

    k_big<64, false><<<NTILES_F/8, 256>>>(fi, fj);
    k_postC<<<NF/8, 256>>>(fc2);

    k_w4<<<NTILES_F/8, 256>>>(W4, fi, fj);
    k_postD<<<NF/256, 256>>>(fc3, out);
}

// round 7
// speedup vs baseline: 2.0740x; 1.2146x over previous
#include <cuda_runtime.h>
#include <stdint.h>

typedef unsigned long long ull;

#define NF 16384
#define NB 4096
#define EF 262144
#define EB 65536
#define EFP16 (EF + 64*16)     // 263168
#define EBP16 (EB + 64*16)     // 66560
#define NT16F (EFP16/16)       // 16448
#define NT16B (EBP16/16)       // 4160
#define T8F (EFP16/8)          // 32896
#define T8B (EBP16/8)          // 8320
#define FULL 0xffffffffu
#define NBLK_F (EF/1024)       // 256
#define NBLK_B (EB/1024)       // 64
#define XSTR 20                // padded cin stride (floats) in k_big smem

// ---------------- scratch ----------------
__device__ __align__(16) float g_ans96 [NF*96];
__device__ __align__(16) float g_ans64a[NF*64];
__device__ __align__(16) float g_ans64b[NF*64];
__device__ __align__(16) float g_acc64a[NF*64];
__device__ __align__(16) float g_acc64b[NF*64];
__device__ __align__(16) float g_acc2  [NF*2];
__device__ __align__(16) float g_W2dup[64*96*128];   // [cell][cin][2*cout] duplicated
__device__ __align__(16) float g_W3dup[64*64*128];
__device__ __align__(16) float4 g_few[EF];
__device__ int   g_febkt[EF];
__device__ __align__(16) float4 g_bew[EB];
__device__ int   g_bbkt[EB];
__device__ int   g_bcnt[64],  g_boff[65],  g_bcur[64];
__device__ int   g_bcntB[64], g_boffB[65], g_bcurB[64];
__device__ int   g_blist[EFP16];
__device__ int   g_blistB[EBP16];
__device__ int   g_tilebkt[NT16F];
__device__ int   g_tilebktB[NT16B];

// ---------------- helpers ----------------
#define FMA2(d,a,b) asm("fma.rn.f32x2 %0, %1, %2, %0;" : "+l"(d) : "l"(a), "l"(b))

__device__ __forceinline__ float2 up2(ull u) {
    float2 f;
    asm("mov.b64 {%0, %1}, %2;" : "=f"(f.x), "=f"(f.y) : "l"(u));
    return f;
}

__device__ __forceinline__ void red2(float* p, float a, float b) {
    asm volatile("red.global.v2.f32.add [%0], {%1, %2};"
                 :: "l"(__cvta_generic_to_global(p)), "f"(a), "f"(b) : "memory");
}

__device__ __forceinline__ void edge_basis(float dx, float dy, int* bkt, float4* w) {
    float r  = sqrtf(dx*dx + dy*dy + 1e-12f);
    float u  = 2.f*r - 1.f;
    float v  = atan2f(dy, dx) * 0.3183098861837907f;
    float tu = (u + 1.f) * 3.5f;
    float tv = (v + 1.f) * 3.5f;
    int iu = (int)floorf(tu); iu = max(0, min(7, iu));
    int iv = (int)floorf(tv); iv = max(0, min(7, iv));
    float wu0 = fmaxf(0.f, 1.f - fabsf(tu - (float)iu));
    float wu1 = (iu < 7) ? fmaxf(0.f, 1.f - fabsf(tu - (float)(iu+1))) : 0.f;
    float wv0 = fmaxf(0.f, 1.f - fabsf(tv - (float)iv));
    float wv1 = (iv < 7) ? fmaxf(0.f, 1.f - fabsf(tv - (float)(iv+1))) : 0.f;
    *bkt = iu*8 + iv;
    *w = make_float4(wu0*wv0, wu0*wv1, wu1*wv0, wu1*wv1);
}

__device__ __forceinline__ void cells_of(int bkt, int* cellIdx) {
    int iu = bkt >> 3, iv = bkt & 7;
    int iu1 = min(iu+1, 7), iv1 = min(iv+1, 7);
    cellIdx[0] = iu*8+iv; cellIdx[1] = iu*8+iv1;
    cellIdx[2] = iu1*8+iv; cellIdx[3] = iu1*8+iv1;
}

// ---------------- zero bucket counters ----------------
__global__ void k_z() {
    int t = threadIdx.x;
    if (t < 64) { g_bcnt[t] = 0; g_bcntB[t] = 0; }
}

// ---------------- init + Wdup + lin (no atomics) ----------------
__global__ void k_pre(const float* __restrict__ ff,
                      const float* __restrict__ W2, const float* __restrict__ W3,
                      const float* __restrict__ fc0) {
    int gt = blockIdx.x * blockDim.x + threadIdx.x;
    int gs = gridDim.x * blockDim.x;
    for (int i = gt; i < NF*64; i += gs) {
        int n = i >> 6, c = i & 63;
        g_ans96[n*96 + 32 + c] = 0.f;   // cols 0..31 fully overwritten by lin
        g_acc64a[i] = 0.f; g_acc64b[i] = 0.f;
    }
    for (int i = gt; i < NF*2;  i += gs) g_acc2[i] = 0.f;
    for (int i = gt; i < EFP16; i += gs) g_blist[i]  = -1;
    for (int i = gt; i < EBP16; i += gs) g_blistB[i] = -1;
    for (int i = gt; i < 64*96*64; i += gs) {
        float w = __ldg(W2 + i);
        ((float2*)g_W2dup)[i] = make_float2(w, w);
    }
    for (int i = gt; i < 64*64*64; i += gs) {
        float w = __ldg(W3 + i);
        ((float2*)g_W3dup)[i] = make_float2(w, w);
    }
    for (int n = gt; n < NF; n += gs) {
        float4 x = *reinterpret_cast<const float4*>(ff + n*4);
        float* o = g_ans96 + n*96;
        #pragma unroll
        for (int co = 0; co < 32; co++) {
            float a = x.x*__ldg(fc0+co) + x.y*__ldg(fc0+32+co)
                    + x.z*__ldg(fc0+64+co) + x.w*__ldg(fc0+96+co);
            o[co] = fmaxf(a, 0.f);
        }
    }
}

// ---------------- edge basis + block-aggregated histogram ----------------
__global__ void __launch_bounds__(256) k_count(const float* __restrict__ fp,
        const float* __restrict__ bp, const float* __restrict__ supp,
        const int* __restrict__ fi, const int* __restrict__ fj,
        const int* __restrict__ bfi, const int* __restrict__ bbi) {
    __shared__ int h[64];
    int tid = threadIdx.x;
    if (tid < 64) h[tid] = 0;
    __syncthreads();
    float s = __ldg(supp);
    bool isB = blockIdx.x >= NBLK_F;
    if (!isB) {
        int base = blockIdx.x * 1024;
        #pragma unroll
        for (int k = 0; k < 4; k++) {
            int e = base + k*256 + tid;
            int a = fi[e], b = fj[e];
            float dx = -(fp[b*2+0] - fp[a*2+0]) / s;
            float dy = -(fp[b*2+1] - fp[a*2+1]) / s;
            dx = fminf(1.f, fmaxf(-1.f, dx)); dy = fminf(1.f, fmaxf(-1.f, dy));
            int bkt; float4 w;
            edge_basis(dx, dy, &bkt, &w);
            g_few[e] = w; g_febkt[e] = bkt;
            atomicAdd(&h[bkt], 1);
        }
        __syncthreads();
        if (tid < 64 && h[tid]) atomicAdd(&g_bcnt[tid], h[tid]);
    } else {
        int base = (blockIdx.x - NBLK_F) * 1024;
        #pragma unroll
        for (int k = 0; k < 4; k++) {
            int e = base + k*256 + tid;
            int a = bfi[e], b = bbi[e];
            float dx = (bp[b*2+0] - fp[a*2+0]) / s;
            float dy = (bp[b*2+1] - fp[a*2+1]) / s;
            dx = fminf(1.f, fmaxf(-1.f, dx)); dy = fminf(1.f, fmaxf(-1.f, dy));
            int bkt; float4 w;
            edge_basis(dx, dy, &bkt, &w);
            g_bew[e] = w; g_bbkt[e] = bkt;
            atomicAdd(&h[bkt], 1);
        }
        __syncthreads();
        if (tid < 64 && h[tid]) atomicAdd(&g_bcntB[tid], h[tid]);
    }
}

// ---------------- scan in smem (padded to 16) ----------------
__global__ void k_scan() {
    __shared__ int c[64], o[65], cB[64], oB[65];
    int t = threadIdx.x;
    if (t < 64)               c[t]      = (g_bcnt[t]     + 15) & ~15;
    else if (t < 128)         cB[t-64]  = (g_bcntB[t-64] + 15) & ~15;
    __syncthreads();
    if (t == 0)  { int s = 0; for (int b = 0; b < 64; b++) { o[b]  = s; s += c[b];  } o[64]  = s; }
    if (t == 32) { int s = 0; for (int b = 0; b < 64; b++) { oB[b] = s; s += cB[b]; } oB[64] = s; }
    __syncthreads();
    if (t < 64)        { g_boff[t]  = o[t];     g_bcur[t]  = o[t]; }
    else if (t == 64)    g_boff[64] = o[64];
    else if (t < 129 && t >= 65) { int b = t - 65; g_boffB[b] = oB[b]; if (b < 64) g_bcurB[b] = oB[b]; }
}

// ---------------- per-16-tile bucket ids: warp-per-bucket direct write ----------------
__global__ void k_tb() {
    int w = (blockIdx.x & 1)*32 + (threadIdx.x >> 5);
    int lane = threadIdx.x & 31;
    if (blockIdx.x < 2) {
        int t0 = g_boff[w] >> 4, t1 = g_boff[w+1] >> 4;
        for (int t = t0 + lane; t < t1; t += 32) g_tilebkt[t] = w;
    } else {
        int t0 = g_boffB[w] >> 4, t1 = g_boffB[w+1] >> 4;
        for (int t = t0 + lane; t < t1; t += 32) g_tilebktB[t] = w;
    }
}

// ---------------- block-aggregated fill ----------------
__global__ void __launch_bounds__(256) k_fillA() {
    __shared__ int h[64], base[64];
    int tid = threadIdx.x;
    if (tid < 64) h[tid] = 0;
    __syncthreads();
    bool isB = blockIdx.x >= NBLK_F;
    const int* bktArr = isB ? g_bbkt  : g_febkt;
    int* cur          = isB ? g_bcurB : g_bcur;
    int* list         = isB ? g_blistB : g_blist;
    int eb = (isB ? (blockIdx.x - NBLK_F) : blockIdx.x) * 1024;
    int myb[4];
    #pragma unroll
    for (int k = 0; k < 4; k++) {
        myb[k] = bktArr[eb + k*256 + tid];
        atomicAdd(&h[myb[k]], 1);
    }
    __syncthreads();
    if (tid < 64) {
        base[tid] = h[tid] ? atomicAdd(&cur[tid], h[tid]) : 0;
        h[tid] = 0;
    }
    __syncthreads();
    #pragma unroll
    for (int k = 0; k < 4; k++) {
        int p = base[myb[k]] + atomicAdd(&h[myb[k]], 1);
        list[p] = eb + k*256 + tid;
    }
}

// ---------------- small convs (cin=4, cout=32): 8-edge tiles, lane=cout ----------------
__global__ void __launch_bounds__(256) k_front(const float* __restrict__ x,
        const float* __restrict__ W, const int* __restrict__ tgt,
        const int* __restrict__ src, int isB, int dstOff) {
    const int* blist    = isB ? g_blistB   : g_blist;
    const int* tb       = isB ? g_tilebktB : g_tilebkt;
    const float4* few   = isB ? g_bew      : g_few;
    __shared__ __align__(16) float4 xf[8][8];
    __shared__ float ws[8][4][8];
    int warp = threadIdx.x >> 5, lane = threadIdx.x & 31;
    int tile = blockIdx.x * 8 + warp;

    int eid = -1, srcv = -1, tgtv = -1; bool valid = false;
    if (lane < 8) {
        eid = blist[tile*8 + lane];
        valid = eid >= 0;
        if (valid) { srcv = src[eid]; tgtv = tgt[eid]; }
        float4 w = valid ? few[eid] : make_float4(0.f,0.f,0.f,0.f);
        ws[warp][0][lane] = w.x; ws[warp][1][lane] = w.y;
        ws[warp][2][lane] = w.z; ws[warp][3][lane] = w.w;
        xf[warp][lane] = valid ? *reinterpret_cast<const float4*>(x + srcv*4)
                               : make_float4(0.f,0.f,0.f,0.f);
    }
    __syncwarp();
    if (__ballot_sync(FULL, valid) == 0) return;
    int cellIdx[4]; cells_of(tb[tile >> 1], cellIdx);

    float acc[8];
    #pragma unroll
    for (int e = 0; e < 8; e++) acc[e] = 0.f;
    #pragma unroll
    for (int c = 0; c < 4; c++) {
        const float* Wc = W + cellIdx[c]*128;    // [cin=4][cout=32]
        float w0 = __ldg(Wc + lane),      w1 = __ldg(Wc + 32 + lane);
        float w2 = __ldg(Wc + 64 + lane), w3 = __ldg(Wc + 96 + lane);
        #pragma unroll
        for (int e = 0; e < 8; e++) {
            float4 xv = xf[warp][e];
            float s = fmaf(xv.x, w0, fmaf(xv.y, w1, fmaf(xv.z, w2, xv.w*w3)));
            acc[e] = fmaf(ws[warp][c][e], s, acc[e]);
        }
    }
    #pragma unroll
    for (int e = 0; e < 8; e++) {
        float v  = acc[e];
        float nb = __shfl_down_sync(FULL, v, 1);
        int t = __shfl_sync(FULL, tgtv, e);
        if (t >= 0 && (lane & 1) == 0)
            red2(g_ans96 + t*96 + dstOff + lane, v, nb);
    }
}

// ---------------- big convs (cout=64): 16-edge tiles, FFMA2, 128-thr CTAs ----------------
template<int CIN, bool RELU>
__global__ void __launch_bounds__(128) k_big(const int* __restrict__ fi,
                                             const int* __restrict__ fj) {
    const float* x  = (CIN == 96) ? g_ans96  : g_ans64a;
    const float* Wd = (CIN == 96) ? g_W2dup  : g_W3dup;
    float* out      = (CIN == 96) ? g_acc64a : g_acc64b;

    __shared__ __align__(16) float xs[4][CIN*XSTR];   // cin stride 20 (conflict 4-way)
    __shared__ __align__(16) float ws[4][4][16];
    int warp = threadIdx.x >> 5, lane = threadIdx.x & 31;
    int tile = blockIdx.x * 4 + warp;

    int eid = -1, srcv = -1, tgtv = -1; bool valid = false;
    if (lane < 16) {
        eid = g_blist[tile*16 + lane];
        valid = eid >= 0;
        if (valid) { srcv = fj[eid]; tgtv = fi[eid]; }
        float4 w = valid ? g_few[eid] : make_float4(0.f,0.f,0.f,0.f);
        ws[warp][0][lane] = w.x; ws[warp][1][lane] = w.y;
        ws[warp][2][lane] = w.z; ws[warp][3][lane] = w.w;
    }
    if (__ballot_sync(FULL, valid) == 0) return;

    // gather x rows coalesced, transpose into xs[cin*XSTR + e]
    #pragma unroll
    for (int e = 0; e < 16; e++) {
        int s = __shfl_sync(FULL, srcv, e);
        #pragma unroll
        for (int k = 0; k < CIN/32; k++) {
            float v = 0.f;
            if (s >= 0) {
                v = __ldg(x + s*CIN + k*32 + lane);
                if (RELU) v = fmaxf(v, 0.f);
            }
            xs[warp][(k*32 + lane)*XSTR + e] = v;
        }
    }
    __syncwarp();

    int cellIdx[4]; cells_of(g_tilebkt[tile], cellIdx);

    ull acc[8][2];
    #pragma unroll
    for (int p = 0; p < 8; p++) { acc[p][0] = 0ull; acc[p][1] = 0ull; }

    const ulonglong2* xp = reinterpret_cast<const ulonglong2*>(xs[warp]);
    #pragma unroll
    for (int c = 0; c < 4; c++) {
        const ulonglong2* Wc = reinterpret_cast<const ulonglong2*>(Wd)
                             + (size_t)cellIdx[c]*(CIN*32) + lane;
        ull tmp[8][2];
        #pragma unroll
        for (int p = 0; p < 8; p++) { tmp[p][0] = 0ull; tmp[p][1] = 0ull; }
        #pragma unroll 2
        for (int cin = 0; cin < CIN; cin++) {
            ulonglong2 wd = __ldg(Wc + cin*32);      // {w0,w0},{w1,w1}
            ulonglong2 x0 = xp[cin*(XSTR/4) + 0];    // e0..e3
            ulonglong2 x1 = xp[cin*(XSTR/4) + 1];    // e4..e7
            ulonglong2 x2 = xp[cin*(XSTR/4) + 2];    // e8..e11
            ulonglong2 x3 = xp[cin*(XSTR/4) + 3];    // e12..e15
            FMA2(tmp[0][0], x0.x, wd.x); FMA2(tmp[0][1], x0.x, wd.y);
            FMA2(tmp[1][0], x0.y, wd.x); FMA2(tmp[1][1], x0.y, wd.y);
            FMA2(tmp[2][0], x1.x, wd.x); FMA2(tmp[2][1], x1.x, wd.y);
            FMA2(tmp[3][0], x1.y, wd.x); FMA2(tmp[3][1], x1.y, wd.y);
            FMA2(tmp[4][0], x2.x, wd.x); FMA2(tmp[4][1], x2.x, wd.y);
            FMA2(tmp[5][0], x2.y, wd.x); FMA2(tmp[5][1], x2.y, wd.y);
            FMA2(tmp[6][0], x3.x, wd.x); FMA2(tmp[6][1], x3.x, wd.y);
            FMA2(tmp[7][0], x3.y, wd.x); FMA2(tmp[7][1], x3.y, wd.y);
        }
        const ull* wsp = reinterpret_cast<const ull*>(ws[warp][c]);
        #pragma unroll
        for (int p = 0; p < 8; p++) {
            ull wp = wsp[p];
            FMA2(acc[p][0], wp, tmp[p][0]);
            FMA2(acc[p][1], wp, tmp[p][1]);
        }
    }
    #pragma unroll
    for (int e = 0; e < 16; e++) {
        int t = __shfl_sync(FULL, tgtv, e);
        if (t >= 0) {
            int p = e >> 1, h = e & 1;
            float2 a = up2(acc[p][0]);
            float2 b = up2(acc[p][1]);
            red2(out + t*64 + lane*2, h ? a.y : a.x, h ? b.y : b.x);
        }
    }
}

// ---------------- W4 conv (cin=64, cout=2): 8-edge tiles, lane=(cell,edge) ----------------
__global__ void __launch_bounds__(256) k_w4(const float* __restrict__ W4,
        const int* __restrict__ fi, const int* __restrict__ fj) {
    __shared__ float xs[8][8][65];
    __shared__ float ws[8][4][8];
    int warp = threadIdx.x >> 5, lane = threadIdx.x & 31;
    int tile = blockIdx.x * 8 + warp;

    int eid = -1, srcv = -1, tgtv = -1; bool valid = false;
    if (lane < 8) {
        eid = g_blist[tile*8 + lane];
        valid = eid >= 0;
        if (valid) { srcv = fj[eid]; tgtv = fi[eid]; }
        float4 w = valid ? g_few[eid] : make_float4(0.f,0.f,0.f,0.f);
        ws[warp][0][lane] = w.x; ws[warp][1][lane] = w.y;
        ws[warp][2][lane] = w.z; ws[warp][3][lane] = w.w;
    }
    if (__ballot_sync(FULL, valid) == 0) return;
    #pragma unroll
    for (int e = 0; e < 8; e++) {
        int s = __shfl_sync(FULL, srcv, e);
        #pragma unroll
        for (int k = 0; k < 2; k++)
            xs[warp][e][k*32 + lane] = (s >= 0) ? __ldg(g_ans64b + s*64 + k*32 + lane) : 0.f;
    }
    __syncwarp();
    int cellIdx[4]; cells_of(g_tilebkt[tile >> 1], cellIdx);

    int c = lane >> 3, e = lane & 7;
    const float2* Wc = reinterpret_cast<const float2*>(W4) + cellIdx[c]*64;
    float t0 = 0.f, t1 = 0.f;
    #pragma unroll 8
    for (int cin = 0; cin < 64; cin++) {
        float xv = xs[warp][e][cin];
        float2 wv = __ldg(Wc + cin);
        t0 = fmaf(xv, wv.x, t0); t1 = fmaf(xv, wv.y, t1);
    }
    float wc = ws[warp][c][e];
    t0 *= wc; t1 *= wc;
    t0 += __shfl_xor_sync(FULL, t0, 8);  t1 += __shfl_xor_sync(FULL, t1, 8);
    t0 += __shfl_xor_sync(FULL, t0, 16); t1 += __shfl_xor_sync(FULL, t1, 16);
    if (lane < 8 && tgtv >= 0) red2(g_acc2 + tgtv*2, t0, t1);
}

// ---------------- dense epilogues ----------------
__global__ void k_postB(const float* __restrict__ fc1) {
    int warp = threadIdx.x >> 5, lane = threadIdx.x & 31;
    int n = blockIdx.x * 8 + warp;
    const float* xrow = g_ans96 + n*96;
    float a0 = 0.f, a1 = 0.f;
    #pragma unroll
    for (int k = 0; k < 96; k += 32) {
        float xv = fmaxf(xrow[k + lane], 0.f);
        #pragma unroll
        for (int j = 0; j < 32; j++) {
            float xj = __shfl_sync(FULL, xv, j);
            float2 f = __ldg(reinterpret_cast<const float2*>(fc1 + (k+j)*64 + lane*2));
            a0 = fmaf(xj, f.x, a0); a1 = fmaf(xj, f.y, a1);
        }
    }
    float2 c = *reinterpret_cast<const float2*>(g_acc64a + n*64 + lane*2);
    float* o = g_ans64a + n*64 + lane*2;
    o[0] = fmaxf(c.x + a0, 0.f);
    o[1] = fmaxf(c.y + a1, 0.f);
}

__global__ void k_postC(const float* __restrict__ fc2) {
    int warp = threadIdx.x >> 5, lane = threadIdx.x & 31;
    int n = blockIdx.x * 8 + warp;
    const float* xrow = g_ans64a + n*64;
    float a0 = 0.f, a1 = 0.f;
    #pragma unroll
    for (int k = 0; k < 64; k += 32) {
        float xv = xrow[k + lane];
        #pragma unroll
        for (int j = 0; j < 32; j++) {
            float xj = __shfl_sync(FULL, xv, j);
            float2 f = __ldg(reinterpret_cast<const float2*>(fc2 + (k+j)*64 + lane*2));
            a0 = fmaf(xj, f.x, a0); a1 = fmaf(xj, f.y, a1);
        }
    }
    float2 c  = *reinterpret_cast<const float2*>(g_acc64b + n*64 + lane*2);
    float2 xr = *reinterpret_cast<const float2*>(g_ans64a + n*64 + lane*2);
    float* o = g_ans64b + n*64 + lane*2;
    o[0] = fmaxf(c.x + a0 + xr.x, 0.f);
    o[1] = fmaxf(c.y + a1 + xr.y, 0.f);
}

__global__ void k_postD(const float* __restrict__ fc3, float* __restrict__ out) {
    int n = blockIdx.x * blockDim.x + threadIdx.x;
    if (n >= NF) return;
    const float* x = g_ans64b + n*64;
    float a0 = 0.f, a1 = 0.f;
    #pragma unroll 8
    for (int cin = 0; cin < 64; cin++) {
        float xv = x[cin];
        float2 f = __ldg(reinterpret_cast<const float2*>(fc3 + cin*2));
        a0 = fmaf(xv, f.x, a0); a1 = fmaf(xv, f.y, a1);
    }
    out[n*2]     = g_acc2[n*2]     + a0;
    out[n*2 + 1] = g_acc2[n*2 + 1] + a1;
}

// ---------------- launch ----------------
extern "C" void kernel_launch(void* const* d_in, const int* in_sizes, int n_in,
                              void* d_out, int out_size) {
    (void)in_sizes; (void)n_in; (void)out_size;
    const float* fp    = (const float*)d_in[0];
    const float* bp    = (const float*)d_in[1];
    const float* ff    = (const float*)d_in[2];
    const float* bfeat = (const float*)d_in[3];
    const float* supp  = (const float*)d_in[4];
    const int*   fi    = (const int*)d_in[5];
    const int*   fj    = (const int*)d_in[6];
    const int*   bf    = (const int*)d_in[7];
    const int*   bb    = (const int*)d_in[8];
    const float* W0    = (const float*)d_in[9];
    const float* W1    = (const float*)d_in[10];
    const float* W2    = (const float*)d_in[11];
    const float* W3    = (const float*)d_in[12];
    const float* W4    = (const float*)d_in[13];
    const float* fc0   = (const float*)d_in[14];
    const float* fc1   = (const float*)d_in[15];
    const float* fc2   = (const float*)d_in[16];
    const float* fc3   = (const float*)d_in[17];
    float* out = (float*)d_out;

    k_z<<<1, 128>>>();
    k_pre<<<1024, 256>>>(ff, W2, W3, fc0);
    k_count<<<NBLK_F + NBLK_B, 256>>>(fp, bp, supp, fi, fj, bf, bb);
    k_scan<<<1, 160>>>();
    k_tb<<<4, 1024>>>();
    k_fillA<<<NBLK_F + NBLK_B, 256>>>();

    k_front<<<T8F/8, 256>>>(ff,    W0, fi, fj, 0, 32);
    k_front<<<T8B/8, 256>>>(bfeat, W1, bf, bb, 1, 64);

    k_big<96, true ><<<NT16F/4, 128>>>(fi, fj);
    k_postB<<<NF/8, 256>>>(fc1);

    k_big<64, false><<<NT16F/4, 128>>>(fi, fj);
    k_postC<<<NF/8, 256>>>(fc2);

    k_w4<<<T8F/8, 256>>>(W4, fi, fj);
    k_postD<<<NF/256, 256>>>(fc3, out);
}

// round 9
// speedup vs baseline: 3.9686x; 1.9135x over previous
#include <cuda_runtime.h>
#include <cuda_bf16.h>
#include <stdint.h>

typedef unsigned long long ull;

#define NF 16384
#define NB 4096
#define EF 262144
#define EB 65536
#define EFP128 (EF + 64*128)   // 270336
#define EBP16  (EB + 64*16)    // 66560
#define NT128  (EFP128/128)    // 2112
#define T8F    (EFP128/8)      // 33792
#define T8B    (EBP16/8)       // 8320
#define NT16B  (EBP16/16)      // 4160
#define FULL 0xffffffffu
#define NBLK_F (EF/1024)       // 256
#define NBLK_B (EB/1024)       // 64

// ---------------- scratch ----------------
__device__ __align__(16) float g_ans96 [NF*96];
__device__ __align__(16) float g_ans64a[NF*64];
__device__ __align__(16) float g_ans64b[NF*64];
__device__ __align__(16) float g_acc64a[NF*64];
__device__ __align__(16) float g_acc64b[NF*64];
__device__ __align__(16) float g_acc2  [NF*2];
// B operands pre-packed in mma.sync fragment order: [cell][hl][kt][nt][lane] -> uint2
__device__ __align__(16) uint2 g_W2F[64*2*6*8*32];   // 1.5 MB
__device__ __align__(16) uint2 g_W3F[64*2*4*8*32];   // 1.0 MB
__device__ __align__(16) float4 g_few[EF];
__device__ int   g_febkt[EF];
__device__ __align__(16) float4 g_bew[EB];
__device__ int   g_bbkt[EB];
__device__ int   g_bcnt[64],  g_boff[65],  g_bcur[64];
__device__ int   g_bcntB[64], g_boffB[65], g_bcurB[64];
__device__ int   g_blist[EFP128];
__device__ int   g_blistB[EBP16];
__device__ int   g_tb128[NT128];
__device__ int   g_tilebktB[NT16B];

// ---------------- helpers ----------------
__device__ __forceinline__ void red2(float* p, float a, float b) {
    asm volatile("red.global.v2.f32.add [%0], {%1, %2};"
                 :: "l"(__cvta_generic_to_global(p)), "f"(a), "f"(b) : "memory");
}

__device__ __forceinline__ uint32_t smem_u32(const void* p) {
    uint32_t a;
    asm("{ .reg .u64 t; cvta.to.shared.u64 t, %1; cvt.u32.u64 %0, t; }" : "=r"(a) : "l"(p));
    return a;
}

#define LDM4(r, addr) \
    asm volatile("ldmatrix.sync.aligned.m8n8.x4.shared.b16 {%0,%1,%2,%3}, [%4];" \
        : "=r"((r)[0]), "=r"((r)[1]), "=r"((r)[2]), "=r"((r)[3]) : "r"(addr))

#define MMA16816(d, a, b0, b1) \
    asm volatile("mma.sync.aligned.m16n8k16.row.col.f32.bf16.bf16.f32 " \
        "{%0,%1,%2,%3}, {%4,%5,%6,%7}, {%8,%9}, {%0,%1,%2,%3};" \
        : "+f"((d)[0]), "+f"((d)[1]), "+f"((d)[2]), "+f"((d)[3]) \
        : "r"((a)[0]), "r"((a)[1]), "r"((a)[2]), "r"((a)[3]), "r"(b0), "r"(b1))

__device__ __forceinline__ uint32_t packh(float a, float b) {
    __nv_bfloat16 ha = __float2bfloat16(a), hb = __float2bfloat16(b);
    return (uint32_t)__bfloat16_as_ushort(ha) | ((uint32_t)__bfloat16_as_ushort(hb) << 16);
}
__device__ __forceinline__ uint32_t packl(float a, float b) {
    __nv_bfloat16 ha = __float2bfloat16(a), hb = __float2bfloat16(b);
    return packh(a - __bfloat162float(ha), b - __bfloat162float(hb));
}

__device__ __forceinline__ void edge_basis(float dx, float dy, int* bkt, float4* w) {
    float r  = sqrtf(dx*dx + dy*dy + 1e-12f);
    float u  = 2.f*r - 1.f;
    float v  = atan2f(dy, dx) * 0.3183098861837907f;
    float tu = (u + 1.f) * 3.5f;
    float tv = (v + 1.f) * 3.5f;
    int iu = (int)floorf(tu); iu = max(0, min(7, iu));
    int iv = (int)floorf(tv); iv = max(0, min(7, iv));
    float wu0 = fmaxf(0.f, 1.f - fabsf(tu - (float)iu));
    float wu1 = (iu < 7) ? fmaxf(0.f, 1.f - fabsf(tu - (float)(iu+1))) : 0.f;
    float wv0 = fmaxf(0.f, 1.f - fabsf(tv - (float)iv));
    float wv1 = (iv < 7) ? fmaxf(0.f, 1.f - fabsf(tv - (float)(iv+1))) : 0.f;
    *bkt = iu*8 + iv;
    *w = make_float4(wu0*wv0, wu0*wv1, wu1*wv0, wu1*wv1);
}

__device__ __forceinline__ void cells_of(int bkt, int* cellIdx) {
    int iu = bkt >> 3, iv = bkt & 7;
    int iu1 = min(iu+1, 7), iv1 = min(iv+1, 7);
    cellIdx[0] = iu*8+iv; cellIdx[1] = iu*8+iv1;
    cellIdx[2] = iu1*8+iv; cellIdx[3] = iu1*8+iv1;
}

// ---------------- zero bucket counters ----------------
__global__ void k_z() {
    int t = threadIdx.x;
    if (t < 64) { g_bcnt[t] = 0; g_bcntB[t] = 0; }
}

// ---------------- init + W-frag prep + lin ----------------
__global__ void k_pre(const float* __restrict__ ff,
                      const float* __restrict__ W2, const float* __restrict__ W3,
                      const float* __restrict__ fc0) {
    int gt = blockIdx.x * blockDim.x + threadIdx.x;
    int gs = gridDim.x * blockDim.x;
    for (int i = gt; i < NF*64; i += gs) {
        int n = i >> 6, c = i & 63;
        g_ans96[n*96 + 32 + c] = 0.f;
        g_acc64a[i] = 0.f; g_acc64b[i] = 0.f;
    }
    for (int i = gt; i < NF*2;   i += gs) g_acc2[i] = 0.f;
    for (int i = gt; i < EFP128; i += gs) g_blist[i]  = -1;
    for (int i = gt; i < EBP16;  i += gs) g_blistB[i] = -1;
    // W2 frags: [cell][hl][kt(6)][nt(8)][lane(32)]
    for (int i = gt; i < 64*2*6*8*32; i += gs) {
        int lane = i & 31, nt = (i >> 5) & 7, kt = (i >> 8) % 6;
        int hl = (i / 1536) & 1, cell = i / 3072;
        int n = nt*8 + (lane >> 2), k0 = kt*16 + (lane & 3)*2;
        const float* Wc = W2 + cell*96*64 + n;
        float v00 = __ldg(Wc + k0*64),     v01 = __ldg(Wc + (k0+1)*64);
        float v10 = __ldg(Wc + (k0+8)*64), v11 = __ldg(Wc + (k0+9)*64);
        g_W2F[i] = (hl == 0) ? make_uint2(packh(v00, v01), packh(v10, v11))
                             : make_uint2(packl(v00, v01), packl(v10, v11));
    }
    // W3 frags: [cell][hl][kt(4)][nt(8)][lane(32)]
    for (int i = gt; i < 64*2*4*8*32; i += gs) {
        int lane = i & 31, nt = (i >> 5) & 7, kt = (i >> 8) % 4;
        int hl = (i / 1024) & 1, cell = i / 2048;
        int n = nt*8 + (lane >> 2), k0 = kt*16 + (lane & 3)*2;
        const float* Wc = W3 + cell*64*64 + n;
        float v00 = __ldg(Wc + k0*64),     v01 = __ldg(Wc + (k0+1)*64);
        float v10 = __ldg(Wc + (k0+8)*64), v11 = __ldg(Wc + (k0+9)*64);
        g_W3F[i] = (hl == 0) ? make_uint2(packh(v00, v01), packh(v10, v11))
                             : make_uint2(packl(v00, v01), packl(v10, v11));
    }
    for (int n = gt; n < NF; n += gs) {
        float4 x = *reinterpret_cast<const float4*>(ff + n*4);
        float* o = g_ans96 + n*96;
        #pragma unroll
        for (int co = 0; co < 32; co++) {
            float a = x.x*__ldg(fc0+co) + x.y*__ldg(fc0+32+co)
                    + x.z*__ldg(fc0+64+co) + x.w*__ldg(fc0+96+co);
            o[co] = fmaxf(a, 0.f);
        }
    }
}

// ---------------- edge basis + block-aggregated histogram ----------------
__global__ void __launch_bounds__(256) k_count(const float* __restrict__ fp,
        const float* __restrict__ bp, const float* __restrict__ supp,
        const int* __restrict__ fi, const int* __restrict__ fj,
        const int* __restrict__ bfi, const int* __restrict__ bbi) {
    __shared__ int h[64];
    int tid = threadIdx.x;
    if (tid < 64) h[tid] = 0;
    __syncthreads();
    float s = __ldg(supp);
    bool isB = blockIdx.x >= NBLK_F;
    if (!isB) {
        int base = blockIdx.x * 1024;
        #pragma unroll
        for (int k = 0; k < 4; k++) {
            int e = base + k*256 + tid;
            int a = fi[e], b = fj[e];
            float dx = -(fp[b*2+0] - fp[a*2+0]) / s;
            float dy = -(fp[b*2+1] - fp[a*2+1]) / s;
            dx = fminf(1.f, fmaxf(-1.f, dx)); dy = fminf(1.f, fmaxf(-1.f, dy));
            int bkt; float4 w;
            edge_basis(dx, dy, &bkt, &w);
            g_few[e] = w; g_febkt[e] = bkt;
            atomicAdd(&h[bkt], 1);
        }
        __syncthreads();
        if (tid < 64 && h[tid]) atomicAdd(&g_bcnt[tid], h[tid]);
    } else {
        int base = (blockIdx.x - NBLK_F) * 1024;
        #pragma unroll
        for (int k = 0; k < 4; k++) {
            int e = base + k*256 + tid;
            int a = bfi[e], b = bbi[e];
            float dx = (bp[b*2+0] - fp[a*2+0]) / s;
            float dy = (bp[b*2+1] - fp[a*2+1]) / s;
            dx = fminf(1.f, fmaxf(-1.f, dx)); dy = fminf(1.f, fmaxf(-1.f, dy));
            int bkt; float4 w;
            edge_basis(dx, dy, &bkt, &w);
            g_bew[e] = w; g_bbkt[e] = bkt;
            atomicAdd(&h[bkt], 1);
        }
        __syncthreads();
        if (tid < 64 && h[tid]) atomicAdd(&g_bcntB[tid], h[tid]);
    }
}

// ---------------- scan in smem (fluid pad 128, bdy pad 16) ----------------
__global__ void k_scan() {
    __shared__ int c[64], o[65], cB[64], oB[65];
    int t = threadIdx.x;
    if (t < 64)        c[t]     = (g_bcnt[t]     + 127) & ~127;
    else if (t < 128)  cB[t-64] = (g_bcntB[t-64] + 15)  & ~15;
    __syncthreads();
    if (t == 0)  { int s = 0; for (int b = 0; b < 64; b++) { o[b]  = s; s += c[b];  } o[64]  = s; }
    if (t == 32) { int s = 0; for (int b = 0; b < 64; b++) { oB[b] = s; s += cB[b]; } oB[64] = s; }
    __syncthreads();
    if (t < 64)        { g_boff[t]  = o[t];     g_bcur[t]  = o[t]; }
    else if (t == 64)    g_boff[64] = o[64];
    else if (t < 129 && t >= 65) { int b = t - 65; g_boffB[b] = oB[b]; if (b < 64) g_bcurB[b] = oB[b]; }
}

// ---------------- per-tile bucket ids ----------------
__global__ void k_tb() {
    int w = (blockIdx.x & 1)*32 + (threadIdx.x >> 5);
    int lane = threadIdx.x & 31;
    if (blockIdx.x < 2) {
        int t0 = g_boff[w] >> 7, t1 = g_boff[w+1] >> 7;
        for (int t = t0 + lane; t < t1; t += 32) g_tb128[t] = w;
    } else {
        int t0 = g_boffB[w] >> 4, t1 = g_boffB[w+1] >> 4;
        for (int t = t0 + lane; t < t1; t += 32) g_tilebktB[t] = w;
    }
}

// ---------------- block-aggregated fill ----------------
__global__ void __launch_bounds__(256) k_fillA() {
    __shared__ int h[64], base[64];
    int tid = threadIdx.x;
    if (tid < 64) h[tid] = 0;
    __syncthreads();
    bool isB = blockIdx.x >= NBLK_F;
    const int* bktArr = isB ? g_bbkt  : g_febkt;
    int* cur          = isB ? g_bcurB : g_bcur;
    int* list         = isB ? g_blistB : g_blist;
    int eb = (isB ? (blockIdx.x - NBLK_F) : blockIdx.x) * 1024;
    int myb[4];
    #pragma unroll
    for (int k = 0; k < 4; k++) {
        myb[k] = bktArr[eb + k*256 + tid];
        atomicAdd(&h[myb[k]], 1);
    }
    __syncthreads();
    if (tid < 64) {
        base[tid] = h[tid] ? atomicAdd(&cur[tid], h[tid]) : 0;
        h[tid] = 0;
    }
    __syncthreads();
    #pragma unroll
    for (int k = 0; k < 4; k++) {
        int p = base[myb[k]] + atomicAdd(&h[myb[k]], 1);
        list[p] = eb + k*256 + tid;
    }
}

// ---------------- small convs (cin=4, cout=32): 8-edge tiles ----------------
__global__ void __launch_bounds__(256) k_front(const float* __restrict__ x,
        const float* __restrict__ W, const int* __restrict__ tgt,
        const int* __restrict__ src, int isB, int dstOff) {
    const int* blist  = isB ? g_blistB : g_blist;
    const float4* few = isB ? g_bew    : g_few;
    __shared__ __align__(16) float4 xf[8][8];
    __shared__ float ws[8][4][8];
    int warp = threadIdx.x >> 5, lane = threadIdx.x & 31;
    int tile = blockIdx.x * 8 + warp;

    int eid = -1, srcv = -1, tgtv = -1; bool valid = false;
    if (lane < 8) {
        eid = blist[tile*8 + lane];
        valid = eid >= 0;
        if (valid) { srcv = src[eid]; tgtv = tgt[eid]; }
        float4 w = valid ? few[eid] : make_float4(0.f,0.f,0.f,0.f);
        ws[warp][0][lane] = w.x; ws[warp][1][lane] = w.y;
        ws[warp][2][lane] = w.z; ws[warp][3][lane] = w.w;
        xf[warp][lane] = valid ? *reinterpret_cast<const float4*>(x + srcv*4)
                               : make_float4(0.f,0.f,0.f,0.f);
    }
    __syncwarp();
    if (__ballot_sync(FULL, valid) == 0) return;
    int bkt = isB ? g_tilebktB[tile >> 1] : g_tb128[tile >> 4];
    int cellIdx[4]; cells_of(bkt, cellIdx);

    float acc[8];
    #pragma unroll
    for (int e = 0; e < 8; e++) acc[e] = 0.f;
    #pragma unroll
    for (int c = 0; c < 4; c++) {
        const float* Wc = W + cellIdx[c]*128;
        float w0 = __ldg(Wc + lane),      w1 = __ldg(Wc + 32 + lane);
        float w2 = __ldg(Wc + 64 + lane), w3 = __ldg(Wc + 96 + lane);
        #pragma unroll
        for (int e = 0; e < 8; e++) {
            float4 xv = xf[warp][e];
            float s = fmaf(xv.x, w0, fmaf(xv.y, w1, fmaf(xv.z, w2, xv.w*w3)));
            acc[e] = fmaf(ws[warp][c][e], s, acc[e]);
        }
    }
    #pragma unroll
    for (int e = 0; e < 8; e++) {
        float v  = acc[e];
        float nb = __shfl_down_sync(FULL, v, 1);
        int t = __shfl_sync(FULL, tgtv, e);
        if (t >= 0 && (lane & 1) == 0)
            red2(g_ans96 + t*96 + dstOff + lane, v, nb);
    }
}

// ---------------- big convs: mma.sync bf16 2-way split, 128-edge CTA tiles ----------------
template<int CIN>
__global__ void __launch_bounds__(128) k_mma(const int* __restrict__ fi,
                                             const int* __restrict__ fj) {
    constexpr int KT = CIN / 16;
    constexpr int ASTR = CIN + 8;            // bf16 elems per row (208B / 144B stride)
    constexpr int ABYTES = 128 * ASTR * 2;
    const float* x    = (CIN == 96) ? g_ans96  : g_ans64a;
    const uint2* Wf   = (CIN == 96) ? g_W2F    : g_W3F;
    float* out        = (CIN == 96) ? g_acc64a : g_acc64b;

    extern __shared__ char smem[];
    int*   tgts = (int*)smem;                       // [128]
    float* wsm  = (float*)(smem + 512);             // [4][128]
    unsigned short* Ah = (unsigned short*)(smem + 2560);
    unsigned short* Al = (unsigned short*)(smem + 2560 + ABYTES);
    uint32_t sb = smem_u32(smem);
    uint32_t AhB = sb + 2560, AlB = sb + 2560 + ABYTES;

    int tid = threadIdx.x, wid = tid >> 5, lane = tid & 31;
    int tile = blockIdx.x;

    int eid = g_blist[tile*128 + tid];
    bool valid = eid >= 0;
    int srcv = valid ? fj[eid] : -1;
    tgts[tid] = valid ? fi[eid] : -1;
    float4 wf = valid ? g_few[eid] : make_float4(0.f,0.f,0.f,0.f);
    wsm[0*128 + tid] = wf.x; wsm[1*128 + tid] = wf.y;
    wsm[2*128 + tid] = wf.z; wsm[3*128 + tid] = wf.w;

    // gather x rows (warp w -> rows w*32..+31), split hi/lo bf16 into smem
    int rb = wid * 32;
    for (int r = 0; r < 32; r++) {
        int row = rb + r;
        int s = __shfl_sync(FULL, srcv, r);
        #pragma unroll
        for (int k = 0; k < CIN/32; k++) {
            float v = 0.f;
            if (s >= 0) {
                v = __ldg(x + s*CIN + k*32 + lane);
                if (CIN == 96) v = fmaxf(v, 0.f);
            }
            __nv_bfloat16 h = __float2bfloat16(v);
            __nv_bfloat16 l = __float2bfloat16(v - __bfloat162float(h));
            Ah[row*ASTR + k*32 + lane] = __bfloat16_as_ushort(h);
            Al[row*ASTR + k*32 + lane] = __bfloat16_as_ushort(l);
        }
    }
    __syncthreads();

    int cells[4]; cells_of(g_tb128[tile], cells);

    // ldmatrix per-lane address components
    int rowoff = (lane & 7) + ((lane >> 3) & 1) * 8;
    int coloff = (lane >> 4) * 8;
    uint32_t aH = AhB + (uint32_t)(((rb + rowoff)*ASTR + coloff) << 1);
    uint32_t aL = AlB + (uint32_t)(((rb + rowoff)*ASTR + coloff) << 1);

    #pragma unroll
    for (int h = 0; h < 2; h++) {          // two 32-col sweeps
        float tot[2][4][4];
        #pragma unroll
        for (int mt = 0; mt < 2; mt++)
            #pragma unroll
            for (int n = 0; n < 4; n++)
                #pragma unroll
                for (int q = 0; q < 4; q++) tot[mt][n][q] = 0.f;

        #pragma unroll
        for (int c = 0; c < 4; c++) {
            float D[2][4][4];
            #pragma unroll
            for (int mt = 0; mt < 2; mt++)
                #pragma unroll
                for (int n = 0; n < 4; n++)
                    #pragma unroll
                    for (int q = 0; q < 4; q++) D[mt][n][q] = 0.f;

            const uint2* WcH = Wf + (cells[c]*2 + 0) * (KT*8*32);
            const uint2* WcL = Wf + (cells[c]*2 + 1) * (KT*8*32);
            #pragma unroll
            for (int pass = 0; pass < 3; pass++) {
                uint32_t ab = (pass == 2) ? aL : aH;
                const uint2* Wb = (pass == 1) ? WcL : WcH;
                #pragma unroll
                for (int kt = 0; kt < KT; kt++) {
                    uint32_t a0[4], a1[4];
                    LDM4(a0, ab + (uint32_t)((kt*16) << 1));
                    LDM4(a1, ab + (uint32_t)((16*ASTR + kt*16) << 1));
                    #pragma unroll
                    for (int nl = 0; nl < 4; nl++) {
                        uint2 b = __ldg(&Wb[(kt*8 + h*4 + nl)*32 + lane]);
                        MMA16816(D[0][nl], a0, b.x, b.y);
                        MMA16816(D[1][nl], a1, b.x, b.y);
                    }
                }
            }
            #pragma unroll
            for (int mt = 0; mt < 2; mt++) {
                float w0 = wsm[c*128 + rb + mt*16 + (lane >> 2)];
                float w1 = wsm[c*128 + rb + mt*16 + (lane >> 2) + 8];
                #pragma unroll
                for (int nl = 0; nl < 4; nl++) {
                    tot[mt][nl][0] = fmaf(w0, D[mt][nl][0], tot[mt][nl][0]);
                    tot[mt][nl][1] = fmaf(w0, D[mt][nl][1], tot[mt][nl][1]);
                    tot[mt][nl][2] = fmaf(w1, D[mt][nl][2], tot[mt][nl][2]);
                    tot[mt][nl][3] = fmaf(w1, D[mt][nl][3], tot[mt][nl][3]);
                }
            }
        }
        // scatter
        #pragma unroll
        for (int mt = 0; mt < 2; mt++) {
            int r0 = rb + mt*16 + (lane >> 2);
            int t0 = tgts[r0], t1 = tgts[r0 + 8];
            int cbase = h*32 + (lane & 3)*2;
            #pragma unroll
            for (int nl = 0; nl < 4; nl++) {
                int col = cbase + nl*8;
                if (t0 >= 0) red2(out + t0*64 + col, tot[mt][nl][0], tot[mt][nl][1]);
                if (t1 >= 0) red2(out + t1*64 + col, tot[mt][nl][2], tot[mt][nl][3]);
            }
        }
    }
}

// ---------------- W4 conv (cin=64, cout=2): 8-edge tiles ----------------
__global__ void __launch_bounds__(256) k_w4(const float* __restrict__ W4,
        const int* __restrict__ fi, const int* __restrict__ fj) {
    __shared__ float xs[8][8][65];
    __shared__ float ws[8][4][8];
    int warp = threadIdx.x >> 5, lane = threadIdx.x & 31;
    int tile = blockIdx.x * 8 + warp;

    int eid = -1, srcv = -1, tgtv = -1; bool valid = false;
    if (lane < 8) {
        eid = g_blist[tile*8 + lane];
        valid = eid >= 0;
        if (valid) { srcv = fj[eid]; tgtv = fi[eid]; }
        float4 w = valid ? g_few[eid] : make_float4(0.f,0.f,0.f,0.f);
        ws[warp][0][lane] = w.x; ws[warp][1][lane] = w.y;
        ws[warp][2][lane] = w.z; ws[warp][3][lane] = w.w;
    }
    if (__ballot_sync(FULL, valid) == 0) return;
    #pragma unroll
    for (int e = 0; e < 8; e++) {
        int s = __shfl_sync(FULL, srcv, e);
        #pragma unroll
        for (int k = 0; k < 2; k++)
            xs[warp][e][k*32 + lane] = (s >= 0) ? __ldg(g_ans64b + s*64 + k*32 + lane) : 0.f;
    }
    __syncwarp();
    int cellIdx[4]; cells_of(g_tb128[tile >> 4], cellIdx);

    int c = lane >> 3, e = lane & 7;
    const float2* Wc = reinterpret_cast<const float2*>(W4) + cellIdx[c]*64;
    float t0 = 0.f, t1 = 0.f;
    #pragma unroll 8
    for (int cin = 0; cin < 64; cin++) {
        float xv = xs[warp][e][cin];
        float2 wv = __ldg(Wc + cin);
        t0 = fmaf(xv, wv.x, t0); t1 = fmaf(xv, wv.y, t1);
    }
    float wcc = ws[warp][c][e];
    t0 *= wcc; t1 *= wcc;
    t0 += __shfl_xor_sync(FULL, t0, 8);  t1 += __shfl_xor_sync(FULL, t1, 8);
    t0 += __shfl_xor_sync(FULL, t0, 16); t1 += __shfl_xor_sync(FULL, t1, 16);
    if (lane < 8 && tgtv >= 0) red2(g_acc2 + tgtv*2, t0, t1);
}

// ---------------- dense epilogues ----------------
__global__ void k_postB(const float* __restrict__ fc1) {
    int warp = threadIdx.x >> 5, lane = threadIdx.x & 31;
    int n = blockIdx.x * 8 + warp;
    const float* xrow = g_ans96 + n*96;
    float a0 = 0.f, a1 = 0.f;
    #pragma unroll
    for (int k = 0; k < 96; k += 32) {
        float xv = fmaxf(xrow[k + lane], 0.f);
        #pragma unroll
        for (int j = 0; j < 32; j++) {
            float xj = __shfl_sync(FULL, xv, j);
            float2 f = __ldg(reinterpret_cast<const float2*>(fc1 + (k+j)*64 + lane*2));
            a0 = fmaf(xj, f.x, a0); a1 = fmaf(xj, f.y, a1);
        }
    }
    float2 c = *reinterpret_cast<const float2*>(g_acc64a + n*64 + lane*2);
    float* o = g_ans64a + n*64 + lane*2;
    o[0] = fmaxf(c.x + a0, 0.f);
    o[1] = fmaxf(c.y + a1, 0.f);
}

__global__ void k_postC(const float* __restrict__ fc2) {
    int warp = threadIdx.x >> 5, lane = threadIdx.x & 31;
    int n = blockIdx.x * 8 + warp;
    const float* xrow = g_ans64a + n*64;
    float a0 = 0.f, a1 = 0.f;
    #pragma unroll
    for (int k = 0; k < 64; k += 32) {
        float xv = xrow[k + lane];
        #pragma unroll
        for (int j = 0; j < 32; j++) {
            float xj = __shfl_sync(FULL, xv, j);
            float2 f = __ldg(reinterpret_cast<const float2*>(fc2 + (k+j)*64 + lane*2));
            a0 = fmaf(xj, f.x, a0); a1 = fmaf(xj, f.y, a1);
        }
    }
    float2 c  = *reinterpret_cast<const float2*>(g_acc64b + n*64 + lane*2);
    float2 xr = *reinterpret_cast<const float2*>(g_ans64a + n*64 + lane*2);
    float* o = g_ans64b + n*64 + lane*2;
    o[0] = fmaxf(c.x + a0 + xr.x, 0.f);
    o[1] = fmaxf(c.y + a1 + xr.y, 0.f);
}

__global__ void k_postD(const float* __restrict__ fc3, float* __restrict__ out) {
    int n = blockIdx.x * blockDim.x + threadIdx.x;
    if (n >= NF) return;
    const float* x = g_ans64b + n*64;
    float a0 = 0.f, a1 = 0.f;
    #pragma unroll 8
    for (int cin = 0; cin < 64; cin++) {
        float xv = x[cin];
        float2 f = __ldg(reinterpret_cast<const float2*>(fc3 + cin*2));
        a0 = fmaf(xv, f.x, a0); a1 = fmaf(xv, f.y, a1);
    }
    out[n*2]     = g_acc2[n*2]     + a0;
    out[n*2 + 1] = g_acc2[n*2 + 1] + a1;
}

// ---------------- launch ----------------
extern "C" void kernel_launch(void* const* d_in, const int* in_sizes, int n_in,
                              void* d_out, int out_size) {
    (void)in_sizes; (void)n_in; (void)out_size;
    const float* fp    = (const float*)d_in[0];
    const float* bp    = (const float*)d_in[1];
    const float* ff    = (const float*)d_in[2];
    const float* bfeat = (const float*)d_in[3];
    const float* supp  = (const float*)d_in[4];
    const int*   fi    = (const int*)d_in[5];
    const int*   fj    = (const int*)d_in[6];
    const int*   bf    = (const int*)d_in[7];
    const int*   bb    = (const int*)d_in[8];
    const float* W0    = (const float*)d_in[9];
    const float* W1    = (const float*)d_in[10];
    const float* W2    = (const float*)d_in[11];
    const float* W3    = (const float*)d_in[12];
    const float* W4    = (const float*)d_in[13];
    const float* fc0   = (const float*)d_in[14];
    const float* fc1   = (const float*)d_in[15];
    const float* fc2   = (const float*)d_in[16];
    const float* fc3   = (const float*)d_in[17];
    float* out = (float*)d_out;

    const int SMEM_96 = 2560 + 2*(128*(96+8)*2);   // 55808
    const int SMEM_64 = 2560 + 2*(128*(64+8)*2);   // 39424
    static bool attrDone = false;
    if (!attrDone) {
        cudaFuncSetAttribute(k_mma<96>, cudaFuncAttributeMaxDynamicSharedMemorySize, SMEM_96);
        cudaFuncSetAttribute(k_mma<64>, cudaFuncAttributeMaxDynamicSharedMemorySize, SMEM_64);
        attrDone = true;
    }

    k_z<<<1, 128>>>();
    k_pre<<<1024, 256>>>(ff, W2, W3, fc0);
    k_count<<<NBLK_F + NBLK_B, 256>>>(fp, bp, supp, fi, fj, bf, bb);
    k_scan<<<1, 160>>>();
    k_tb<<<4, 1024>>>();
    k_fillA<<<NBLK_F + NBLK_B, 256>>>();

    k_front<<<T8F/8, 256>>>(ff,    W0, fi, fj, 0, 32);
    k_front<<<T8B/8, 256>>>(bfeat, W1, bf, bb, 1, 64);

    k_mma<96><<<NT128, 128, SMEM_96>>>(fi, fj);
    k_postB<<<NF/8, 256>>>(fc1);

    k_mma<64><<<NT128, 128, SMEM_64>>>(fi, fj);
    k_postC<<<NF/8, 256>>>(fc2);

    k_w4<<<T8F/8, 256>>>(W4, fi, fj);
    k_postD<<<NF/256, 256>>>(fc3, out);
}

// round 10
// speedup vs baseline: 3.9879x; 1.0049x over previous
#include <cuda_runtime.h>
#include <cuda_bf16.h>
#include <stdint.h>

typedef unsigned long long ull;

#define NF 16384
#define NB 4096
#define EF 262144
#define EB 65536
#define EFP128 (EF + 64*128)   // 270336
#define EBP16  (EB + 64*16)    // 66560
#define NT128  (EFP128/128)    // 2112
#define T8F    (EFP128/8)      // 33792
#define T8B    (EBP16/8)       // 8320
#define NT16B  (EBP16/16)      // 4160
#define FULL 0xffffffffu
#define NBLK_F (EF/1024)       // 256
#define NBLK_B (EB/1024)       // 64

// ---------------- scratch ----------------
__device__ __align__(16) float g_ans96 [NF*96];
__device__ __align__(16) float g_ans64a[NF*64];
__device__ __align__(16) float g_ans64b[NF*64];
__device__ __align__(16) float g_acc64a[NF*64];
__device__ __align__(16) float g_acc64b[NF*64];
__device__ __align__(16) float g_acc2  [NF*2];
// B operands pre-packed in mma.sync fragment order: [cell][hl][kt][nt][lane] -> uint2
__device__ __align__(16) uint2 g_W2F[64*2*6*8*32];
__device__ __align__(16) uint2 g_W3F[64*2*4*8*32];
__device__ __align__(16) float4 g_few[EF];
__device__ int   g_febkt[EF];
__device__ __align__(16) float4 g_bew[EB];
__device__ int   g_bbkt[EB];
__device__ int   g_bcnt[64],  g_boff[65],  g_bcur[64];
__device__ int   g_bcntB[64], g_boffB[65], g_bcurB[64];
__device__ int   g_blist[EFP128];
__device__ int   g_blistB[EBP16];
__device__ int   g_tb128[NT128];
__device__ int   g_tilebktB[NT16B];

// ---------------- helpers ----------------
__device__ __forceinline__ void red2(float* p, float a, float b) {
    asm volatile("red.global.add.v2.f32 [%0], {%1, %2};"
                 :: "l"(__cvta_generic_to_global(p)), "f"(a), "f"(b) : "memory");
}
__device__ __forceinline__ void red4(float* p, float a, float b, float c, float d) {
    asm volatile("red.global.add.v4.f32 [%0], {%1, %2, %3, %4};"
                 :: "l"(__cvta_generic_to_global(p)), "f"(a), "f"(b), "f"(c), "f"(d) : "memory");
}
__device__ __forceinline__ ull pk64(float a, float b) {
    ull u; asm("mov.b64 %0, {%1, %2};" : "=l"(u) : "f"(a), "f"(b)); return u;
}
__device__ __forceinline__ float2 up2(ull u) {
    float2 f; asm("mov.b64 {%0, %1}, %2;" : "=f"(f.x), "=f"(f.y) : "l"(u)); return f;
}

__device__ __forceinline__ uint32_t smem_u32(const void* p) {
    uint32_t a;
    asm("{ .reg .u64 t; cvta.to.shared.u64 t, %1; cvt.u32.u64 %0, t; }" : "=r"(a) : "l"(p));
    return a;
}

#define LDM4(r, addr) \
    asm volatile("ldmatrix.sync.aligned.m8n8.x4.shared.b16 {%0,%1,%2,%3}, [%4];" \
        : "=r"((r)[0]), "=r"((r)[1]), "=r"((r)[2]), "=r"((r)[3]) : "r"(addr))

#define MMA16816(d, a, b0, b1) \
    asm volatile("mma.sync.aligned.m16n8k16.row.col.f32.bf16.bf16.f32 " \
        "{%0,%1,%2,%3}, {%4,%5,%6,%7}, {%8,%9}, {%0,%1,%2,%3};" \
        : "+f"((d)[0]), "+f"((d)[1]), "+f"((d)[2]), "+f"((d)[3]) \
        : "r"((a)[0]), "r"((a)[1]), "r"((a)[2]), "r"((a)[3]), "r"(b0), "r"(b1))

__device__ __forceinline__ uint32_t packh(float a, float b) {
    __nv_bfloat16 ha = __float2bfloat16(a), hb = __float2bfloat16(b);
    return (uint32_t)__bfloat16_as_ushort(ha) | ((uint32_t)__bfloat16_as_ushort(hb) << 16);
}
__device__ __forceinline__ uint32_t packl(float a, float b) {
    __nv_bfloat16 ha = __float2bfloat16(a), hb = __float2bfloat16(b);
    return packh(a - __bfloat162float(ha), b - __bfloat162float(hb));
}

__device__ __forceinline__ void edge_basis(float dx, float dy, int* bkt, float4* w) {
    float r  = sqrtf(dx*dx + dy*dy + 1e-12f);
    float u  = 2.f*r - 1.f;
    float v  = atan2f(dy, dx) * 0.3183098861837907f;
    float tu = (u + 1.f) * 3.5f;
    float tv = (v + 1.f) * 3.5f;
    int iu = (int)floorf(tu); iu = max(0, min(7, iu));
    int iv = (int)floorf(tv); iv = max(0, min(7, iv));
    float wu0 = fmaxf(0.f, 1.f - fabsf(tu - (float)iu));
    float wu1 = (iu < 7) ? fmaxf(0.f, 1.f - fabsf(tu - (float)(iu+1))) : 0.f;
    float wv0 = fmaxf(0.f, 1.f - fabsf(tv - (float)iv));
    float wv1 = (iv < 7) ? fmaxf(0.f, 1.f - fabsf(tv - (float)(iv+1))) : 0.f;
    *bkt = iu*8 + iv;
    *w = make_float4(wu0*wv0, wu0*wv1, wu1*wv0, wu1*wv1);
}

__device__ __forceinline__ void cells_of(int bkt, int* cellIdx) {
    int iu = bkt >> 3, iv = bkt & 7;
    int iu1 = min(iu+1, 7), iv1 = min(iv+1, 7);
    cellIdx[0] = iu*8+iv; cellIdx[1] = iu*8+iv1;
    cellIdx[2] = iu1*8+iv; cellIdx[3] = iu1*8+iv1;
}

// ---------------- init + counter zero + W-frag prep + lin ----------------
__global__ void k_pre(const float* __restrict__ ff,
                      const float* __restrict__ W2, const float* __restrict__ W3,
                      const float* __restrict__ fc0) {
    int gt = blockIdx.x * blockDim.x + threadIdx.x;
    int gs = gridDim.x * blockDim.x;
    if (gt < 64) { g_bcnt[gt] = 0; g_bcntB[gt] = 0; }
    for (int i = gt; i < NF*64; i += gs) {
        int n = i >> 6, c = i & 63;
        g_ans96[n*96 + 32 + c] = 0.f;
        g_acc64a[i] = 0.f; g_acc64b[i] = 0.f;
    }
    for (int i = gt; i < NF*2;   i += gs) g_acc2[i] = 0.f;
    for (int i = gt; i < EFP128; i += gs) g_blist[i]  = -1;
    for (int i = gt; i < EBP16;  i += gs) g_blistB[i] = -1;
    // W2 frags: [cell][hl][kt(6)][nt(8)][lane(32)]
    for (int i = gt; i < 64*2*6*8*32; i += gs) {
        int lane = i & 31, nt = (i >> 5) & 7, kt = (i >> 8) % 6;
        int hl = (i / 1536) & 1, cell = i / 3072;
        int n = nt*8 + (lane >> 2), k0 = kt*16 + (lane & 3)*2;
        const float* Wc = W2 + cell*96*64 + n;
        float v00 = __ldg(Wc + k0*64),     v01 = __ldg(Wc + (k0+1)*64);
        float v10 = __ldg(Wc + (k0+8)*64), v11 = __ldg(Wc + (k0+9)*64);
        g_W2F[i] = (hl == 0) ? make_uint2(packh(v00, v01), packh(v10, v11))
                             : make_uint2(packl(v00, v01), packl(v10, v11));
    }
    // W3 frags: [cell][hl][kt(4)][nt(8)][lane(32)]
    for (int i = gt; i < 64*2*4*8*32; i += gs) {
        int lane = i & 31, nt = (i >> 5) & 7, kt = (i >> 8) % 4;
        int hl = (i / 1024) & 1, cell = i / 2048;
        int n = nt*8 + (lane >> 2), k0 = kt*16 + (lane & 3)*2;
        const float* Wc = W3 + cell*64*64 + n;
        float v00 = __ldg(Wc + k0*64),     v01 = __ldg(Wc + (k0+1)*64);
        float v10 = __ldg(Wc + (k0+8)*64), v11 = __ldg(Wc + (k0+9)*64);
        g_W3F[i] = (hl == 0) ? make_uint2(packh(v00, v01), packh(v10, v11))
                             : make_uint2(packl(v00, v01), packl(v10, v11));
    }
    for (int n = gt; n < NF; n += gs) {
        float4 x = *reinterpret_cast<const float4*>(ff + n*4);
        float* o = g_ans96 + n*96;
        #pragma unroll
        for (int co = 0; co < 32; co++) {
            float a = x.x*__ldg(fc0+co) + x.y*__ldg(fc0+32+co)
                    + x.z*__ldg(fc0+64+co) + x.w*__ldg(fc0+96+co);
            o[co] = fmaxf(a, 0.f);
        }
    }
}

// ---------------- edge basis + block-aggregated histogram ----------------
__global__ void __launch_bounds__(256) k_count(const float* __restrict__ fp,
        const float* __restrict__ bp, const float* __restrict__ supp,
        const int* __restrict__ fi, const int* __restrict__ fj,
        const int* __restrict__ bfi, const int* __restrict__ bbi) {
    __shared__ int h[64];
    int tid = threadIdx.x;
    if (tid < 64) h[tid] = 0;
    __syncthreads();
    float s = __ldg(supp);
    bool isB = blockIdx.x >= NBLK_F;
    if (!isB) {
        int base = blockIdx.x * 1024;
        #pragma unroll
        for (int k = 0; k < 4; k++) {
            int e = base + k*256 + tid;
            int a = fi[e], b = fj[e];
            float dx = -(fp[b*2+0] - fp[a*2+0]) / s;
            float dy = -(fp[b*2+1] - fp[a*2+1]) / s;
            dx = fminf(1.f, fmaxf(-1.f, dx)); dy = fminf(1.f, fmaxf(-1.f, dy));
            int bkt; float4 w;
            edge_basis(dx, dy, &bkt, &w);
            g_few[e] = w; g_febkt[e] = bkt;
            atomicAdd(&h[bkt], 1);
        }
        __syncthreads();
        if (tid < 64 && h[tid]) atomicAdd(&g_bcnt[tid], h[tid]);
    } else {
        int base = (blockIdx.x - NBLK_F) * 1024;
        #pragma unroll
        for (int k = 0; k < 4; k++) {
            int e = base + k*256 + tid;
            int a = bfi[e], b = bbi[e];
            float dx = (bp[b*2+0] - fp[a*2+0]) / s;
            float dy = (bp[b*2+1] - fp[a*2+1]) / s;
            dx = fminf(1.f, fmaxf(-1.f, dx)); dy = fminf(1.f, fmaxf(-1.f, dy));
            int bkt; float4 w;
            edge_basis(dx, dy, &bkt, &w);
            g_bew[e] = w; g_bbkt[e] = bkt;
            atomicAdd(&h[bkt], 1);
        }
        __syncthreads();
        if (tid < 64 && h[tid]) atomicAdd(&g_bcntB[tid], h[tid]);
    }
}

// ---------------- scan (smem) + per-tile bucket ids, one block ----------------
__global__ void __launch_bounds__(1024) k_scan2() {
    __shared__ int c[64], o[65], cB[64], oB[65];
    int t = threadIdx.x;
    if (t < 64)        c[t]     = (g_bcnt[t]     + 127) & ~127;
    else if (t < 128)  cB[t-64] = (g_bcntB[t-64] + 15)  & ~15;
    __syncthreads();
    if (t == 0)  { int s = 0; for (int b = 0; b < 64; b++) { o[b]  = s; s += c[b];  } o[64]  = s; }
    if (t == 32) { int s = 0; for (int b = 0; b < 64; b++) { oB[b] = s; s += cB[b]; } oB[64] = s; }
    __syncthreads();
    if (t < 64)        { g_boff[t]  = o[t];     g_bcur[t]  = o[t]; }
    else if (t == 64)    g_boff[64] = o[64];
    else if (t >= 65 && t < 130) { int b = t - 65; g_boffB[b] = oB[b]; if (b < 64) g_bcurB[b] = oB[b]; }
    int wrp = t >> 5, ln = t & 31;
    for (int b = wrp; b < 64; b += 32) {
        for (int tt = (o[b] >> 7) + ln; tt < (o[b+1] >> 7); tt += 32) g_tb128[tt] = b;
        for (int tt = (oB[b] >> 4) + ln; tt < (oB[b+1] >> 4); tt += 32) g_tilebktB[tt] = b;
    }
}

// ---------------- block-aggregated fill ----------------
__global__ void __launch_bounds__(256) k_fillA() {
    __shared__ int h[64], base[64];
    int tid = threadIdx.x;
    if (tid < 64) h[tid] = 0;
    __syncthreads();
    bool isB = blockIdx.x >= NBLK_F;
    const int* bktArr = isB ? g_bbkt  : g_febkt;
    int* cur          = isB ? g_bcurB : g_bcur;
    int* list         = isB ? g_blistB : g_blist;
    int eb = (isB ? (blockIdx.x - NBLK_F) : blockIdx.x) * 1024;
    int myb[4];
    #pragma unroll
    for (int k = 0; k < 4; k++) {
        myb[k] = bktArr[eb + k*256 + tid];
        atomicAdd(&h[myb[k]], 1);
    }
    __syncthreads();
    if (tid < 64) {
        base[tid] = h[tid] ? atomicAdd(&cur[tid], h[tid]) : 0;
        h[tid] = 0;
    }
    __syncthreads();
    #pragma unroll
    for (int k = 0; k < 4; k++) {
        int p = base[myb[k]] + atomicAdd(&h[myb[k]], 1);
        list[p] = eb + k*256 + tid;
    }
}

// ---------------- small convs (cin=4, cout=32), fluid+bdy in one launch ----------------
__global__ void __launch_bounds__(256) k_front(const float* __restrict__ xF,
        const float* __restrict__ W0, const int* __restrict__ fi, const int* __restrict__ fj,
        const float* __restrict__ xB, const float* __restrict__ W1,
        const int* __restrict__ bfi, const int* __restrict__ bbi) {
    bool isB = blockIdx.x >= (T8F/8);
    const float* x    = isB ? xB : xF;
    const float* W    = isB ? W1 : W0;
    const int* tgt    = isB ? bfi : fi;
    const int* src    = isB ? bbi : fj;
    const int* blist  = isB ? g_blistB : g_blist;
    const float4* few = isB ? g_bew : g_few;
    int dstOff        = isB ? 64 : 32;

    __shared__ __align__(16) float4 xf[8][8];
    __shared__ float ws[8][4][8];
    int warp = threadIdx.x >> 5, lane = threadIdx.x & 31;
    int tile = (isB ? (blockIdx.x - T8F/8) : blockIdx.x) * 8 + warp;

    int eid = -1, srcv = -1, tgtv = -1; bool valid = false;
    if (lane < 8) {
        eid = blist[tile*8 + lane];
        valid = eid >= 0;
        if (valid) { srcv = src[eid]; tgtv = tgt[eid]; }
        float4 w = valid ? few[eid] : make_float4(0.f,0.f,0.f,0.f);
        ws[warp][0][lane] = w.x; ws[warp][1][lane] = w.y;
        ws[warp][2][lane] = w.z; ws[warp][3][lane] = w.w;
        xf[warp][lane] = valid ? *reinterpret_cast<const float4*>(x + srcv*4)
                               : make_float4(0.f,0.f,0.f,0.f);
    }
    __syncwarp();
    if (__ballot_sync(FULL, valid) == 0) return;
    int bkt = isB ? g_tilebktB[tile >> 1] : g_tb128[tile >> 4];
    int cellIdx[4]; cells_of(bkt, cellIdx);

    float acc[8];
    #pragma unroll
    for (int e = 0; e < 8; e++) acc[e] = 0.f;
    #pragma unroll
    for (int c = 0; c < 4; c++) {
        const float* Wc = W + cellIdx[c]*128;
        float w0 = __ldg(Wc + lane),      w1 = __ldg(Wc + 32 + lane);
        float w2 = __ldg(Wc + 64 + lane), w3 = __ldg(Wc + 96 + lane);
        #pragma unroll
        for (int e = 0; e < 8; e++) {
            float4 xv = xf[warp][e];
            float s = fmaf(xv.x, w0, fmaf(xv.y, w1, fmaf(xv.z, w2, xv.w*w3)));
            acc[e] = fmaf(ws[warp][c][e], s, acc[e]);
        }
    }
    #pragma unroll
    for (int e = 0; e < 8; e++) {
        float v  = acc[e];
        float nb = __shfl_down_sync(FULL, v, 1);
        int t = __shfl_sync(FULL, tgtv, e);
        if (t >= 0 && (lane & 1) == 0)
            red2(g_ans96 + t*96 + dstOff + lane, v, nb);
    }
}

// ---------------- big convs: mma.sync bf16 2-way split, A frags cached in regs ----------------
template<int CIN>
__global__ void __launch_bounds__(128) k_mma(const int* __restrict__ fi,
                                             const int* __restrict__ fj) {
    constexpr int KT = CIN / 16;
    constexpr int ASTR = CIN + 8;
    constexpr int ABYTES = 128 * ASTR * 2;
    const float* x    = (CIN == 96) ? g_ans96  : g_ans64a;
    const uint2* Wf   = (CIN == 96) ? g_W2F    : g_W3F;
    float* out        = (CIN == 96) ? g_acc64a : g_acc64b;

    extern __shared__ char smem[];
    int*   tgts = (int*)smem;                       // [128]
    float* wsm  = (float*)(smem + 512);             // [4][128]
    unsigned short* Ah = (unsigned short*)(smem + 2560);
    unsigned short* Al = (unsigned short*)(smem + 2560 + ABYTES);
    uint32_t sb = smem_u32(smem);
    uint32_t AhB = sb + 2560, AlB = sb + 2560 + ABYTES;

    int tid = threadIdx.x, wid = tid >> 5, lane = tid & 31;
    int tile = blockIdx.x;

    int eid = g_blist[tile*128 + tid];
    bool valid = eid >= 0;
    int srcv = valid ? fj[eid] : -1;
    tgts[tid] = valid ? fi[eid] : -1;
    float4 wf = valid ? g_few[eid] : make_float4(0.f,0.f,0.f,0.f);
    wsm[0*128 + tid] = wf.x; wsm[1*128 + tid] = wf.y;
    wsm[2*128 + tid] = wf.z; wsm[3*128 + tid] = wf.w;

    // gather x rows (warp w -> rows w*32..+31), split hi/lo bf16 into smem
    int rb = wid * 32;
    for (int r = 0; r < 32; r++) {
        int row = rb + r;
        int s = __shfl_sync(FULL, srcv, r);
        #pragma unroll
        for (int k = 0; k < CIN/32; k++) {
            float v = 0.f;
            if (s >= 0) {
                v = __ldg(x + s*CIN + k*32 + lane);
                if (CIN == 96) v = fmaxf(v, 0.f);
            }
            __nv_bfloat16 h = __float2bfloat16(v);
            __nv_bfloat16 l = __float2bfloat16(v - __bfloat162float(h));
            Ah[row*ASTR + k*32 + lane] = __bfloat16_as_ushort(h);
            Al[row*ASTR + k*32 + lane] = __bfloat16_as_ushort(l);
        }
    }
    __syncthreads();

    int cells[4]; cells_of(g_tb128[tile], cells);

    // load ALL A fragments into registers (a0: rows rb..+15, a1: rows rb+16..+31)
    int rowoff = (lane & 7) + ((lane >> 3) & 1) * 8;
    int coloff = (lane >> 4) * 8;
    uint32_t aH = AhB + (uint32_t)(((rb + rowoff)*ASTR + coloff) << 1);
    uint32_t aL = AlB + (uint32_t)(((rb + rowoff)*ASTR + coloff) << 1);
    uint32_t afH[KT][8], afL[KT][8];
    #pragma unroll
    for (int kt = 0; kt < KT; kt++) {
        LDM4(&afH[kt][0], aH + (uint32_t)((kt*16) << 1));
        LDM4(&afH[kt][4], aH + (uint32_t)((16*ASTR + kt*16) << 1));
        LDM4(&afL[kt][0], aL + (uint32_t)((kt*16) << 1));
        LDM4(&afL[kt][4], aL + (uint32_t)((16*ASTR + kt*16) << 1));
    }

    #pragma unroll
    for (int h = 0; h < 2; h++) {
        float tot[2][4][4];
        #pragma unroll
        for (int mt = 0; mt < 2; mt++)
            #pragma unroll
            for (int n = 0; n < 4; n++)
                #pragma unroll
                for (int q = 0; q < 4; q++) tot[mt][n][q] = 0.f;

        #pragma unroll
        for (int c = 0; c < 4; c++) {
            float D[2][4][4];
            #pragma unroll
            for (int mt = 0; mt < 2; mt++)
                #pragma unroll
                for (int n = 0; n < 4; n++)
                    #pragma unroll
                    for (int q = 0; q < 4; q++) D[mt][n][q] = 0.f;

            const uint2* WcH = Wf + (cells[c]*2 + 0) * (KT*8*32);
            const uint2* WcL = Wf + (cells[c]*2 + 1) * (KT*8*32);
            #pragma unroll
            for (int pass = 0; pass < 3; pass++) {
                const uint2* Wb = (pass == 1) ? WcL : WcH;
                #pragma unroll
                for (int kt = 0; kt < KT; kt++) {
                    const uint32_t* a0 = (pass == 2) ? &afL[kt][0] : &afH[kt][0];
                    const uint32_t* a1 = (pass == 2) ? &afL[kt][4] : &afH[kt][4];
                    #pragma unroll
                    for (int nl = 0; nl < 4; nl++) {
                        uint2 b = __ldg(&Wb[(kt*8 + h*4 + nl)*32 + lane]);
                        MMA16816(D[0][nl], a0, b.x, b.y);
                        MMA16816(D[1][nl], a1, b.x, b.y);
                    }
                }
            }
            #pragma unroll
            for (int mt = 0; mt < 2; mt++) {
                float w0 = wsm[c*128 + rb + mt*16 + (lane >> 2)];
                float w1 = wsm[c*128 + rb + mt*16 + (lane >> 2) + 8];
                #pragma unroll
                for (int nl = 0; nl < 4; nl++) {
                    tot[mt][nl][0] = fmaf(w0, D[mt][nl][0], tot[mt][nl][0]);
                    tot[mt][nl][1] = fmaf(w0, D[mt][nl][1], tot[mt][nl][1]);
                    tot[mt][nl][2] = fmaf(w1, D[mt][nl][2], tot[mt][nl][2]);
                    tot[mt][nl][3] = fmaf(w1, D[mt][nl][3], tot[mt][nl][3]);
                }
            }
        }
        // scatter: merge lane pairs (cols +0..1 with +2..3) -> red.v4 from even lanes
        #pragma unroll
        for (int mt = 0; mt < 2; mt++) {
            int r0 = rb + mt*16 + (lane >> 2);
            int tA = tgts[r0], tB = tgts[r0 + 8];
            #pragma unroll
            for (int rs = 0; rs < 2; rs++) {
                int tt = rs ? tB : tA;
                #pragma unroll
                for (int nl = 0; nl < 4; nl++) {
                    ull mine = pk64(tot[mt][nl][rs*2], tot[mt][nl][rs*2 + 1]);
                    ull oth  = __shfl_down_sync(FULL, mine, 1);
                    if (!(lane & 1) && tt >= 0) {
                        float2 m = up2(mine), o = up2(oth);
                        red4(out + tt*64 + h*32 + nl*8 + (lane & 2)*2, m.x, m.y, o.x, o.y);
                    }
                }
            }
        }
    }
}

// ---------------- W4 conv (cin=64, cout=2): 8-edge tiles ----------------
__global__ void __launch_bounds__(256) k_w4(const float* __restrict__ W4,
        const int* __restrict__ fi, const int* __restrict__ fj) {
    __shared__ float xs[8][8][65];
    __shared__ float ws[8][4][8];
    int warp = threadIdx.x >> 5, lane = threadIdx.x & 31;
    int tile = blockIdx.x * 8 + warp;

    int eid = -1, srcv = -1, tgtv = -1; bool valid = false;
    if (lane < 8) {
        eid = g_blist[tile*8 + lane];
        valid = eid >= 0;
        if (valid) { srcv = fj[eid]; tgtv = fi[eid]; }
        float4 w = valid ? g_few[eid] : make_float4(0.f,0.f,0.f,0.f);
        ws[warp][0][lane] = w.x; ws[warp][1][lane] = w.y;
        ws[warp][2][lane] = w.z; ws[warp][3][lane] = w.w;
    }
    if (__ballot_sync(FULL, valid) == 0) return;
    #pragma unroll
    for (int e = 0; e < 8; e++) {
        int s = __shfl_sync(FULL, srcv, e);
        #pragma unroll
        for (int k = 0; k < 2; k++)
            xs[warp][e][k*32 + lane] = (s >= 0) ? __ldg(g_ans64b + s*64 + k*32 + lane) : 0.f;
    }
    __syncwarp();
    int cellIdx[4]; cells_of(g_tb128[tile >> 4], cellIdx);

    int c = lane >> 3, e = lane & 7;
    const float2* Wc = reinterpret_cast<const float2*>(W4) + cellIdx[c]*64;
    float t0 = 0.f, t1 = 0.f;
    #pragma unroll 8
    for (int cin = 0; cin < 64; cin++) {
        float xv = xs[warp][e][cin];
        float2 wv = __ldg(Wc + cin);
        t0 = fmaf(xv, wv.x, t0); t1 = fmaf(xv, wv.y, t1);
    }
    float wcc = ws[warp][c][e];
    t0 *= wcc; t1 *= wcc;
    t0 += __shfl_xor_sync(FULL, t0, 8);  t1 += __shfl_xor_sync(FULL, t1, 8);
    t0 += __shfl_xor_sync(FULL, t0, 16); t1 += __shfl_xor_sync(FULL, t1, 16);
    if (lane < 8 && tgtv >= 0) red2(g_acc2 + tgtv*2, t0, t1);
}

// ---------------- dense epilogues ----------------
__global__ void k_postB(const float* __restrict__ fc1) {
    int warp = threadIdx.x >> 5, lane = threadIdx.x & 31;
    int n = blockIdx.x * 8 + warp;
    const float* xrow = g_ans96 + n*96;
    float a0 = 0.f, a1 = 0.f;
    #pragma unroll
    for (int k = 0; k < 96; k += 32) {
        float xv = fmaxf(xrow[k + lane], 0.f);
        #pragma unroll
        for (int j = 0; j < 32; j++) {
            float xj = __shfl_sync(FULL, xv, j);
            float2 f = __ldg(reinterpret_cast<const float2*>(fc1 + (k+j)*64 + lane*2));
            a0 = fmaf(xj, f.x, a0); a1 = fmaf(xj, f.y, a1);
        }
    }
    float2 c = *reinterpret_cast<const float2*>(g_acc64a + n*64 + lane*2);
    float* o = g_ans64a + n*64 + lane*2;
    o[0] = fmaxf(c.x + a0, 0.f);
    o[1] = fmaxf(c.y + a1, 0.f);
}

__global__ void k_postC(const float* __restrict__ fc2) {
    int warp = threadIdx.x >> 5, lane = threadIdx.x & 31;
    int n = blockIdx.x * 8 + warp;
    const float* xrow = g_ans64a + n*64;
    float a0 = 0.f, a1 = 0.f;
    #pragma unroll
    for (int k = 0; k < 64; k += 32) {
        float xv = xrow[k + lane];
        #pragma unroll
        for (int j = 0; j < 32; j++) {
            float xj = __shfl_sync(FULL, xv, j);
            float2 f = __ldg(reinterpret_cast<const float2*>(fc2 + (k+j)*64 + lane*2));
            a0 = fmaf(xj, f.x, a0); a1 = fmaf(xj, f.y, a1);
        }
    }
    float2 c  = *reinterpret_cast<const float2*>(g_acc64b + n*64 + lane*2);
    float2 xr = *reinterpret_cast<const float2*>(g_ans64a + n*64 + lane*2);
    float* o = g_ans64b + n*64 + lane*2;
    o[0] = fmaxf(c.x + a0 + xr.x, 0.f);
    o[1] = fmaxf(c.y + a1 + xr.y, 0.f);
}

__global__ void k_postD(const float* __restrict__ fc3, float* __restrict__ out) {
    int n = blockIdx.x * blockDim.x + threadIdx.x;
    if (n >= NF) return;
    const float* x = g_ans64b + n*64;
    float a0 = 0.f, a1 = 0.f;
    #pragma unroll 8
    for (int cin = 0; cin < 64; cin++) {
        float xv = x[cin];
        float2 f = __ldg(reinterpret_cast<const float2*>(fc3 + cin*2));
        a0 = fmaf(xv, f.x, a0); a1 = fmaf(xv, f.y, a1);
    }
    out[n*2]     = g_acc2[n*2]     + a0;
    out[n*2 + 1] = g_acc2[n*2 + 1] + a1;
}

// ---------------- launch ----------------
extern "C" void kernel_launch(void* const* d_in, const int* in_sizes, int n_in,
                              void* d_out, int out_size) {
    (void)in_sizes; (void)n_in; (void)out_size;
    const float* fp    = (const float*)d_in[0];
    const float* bp    = (const float*)d_in[1];
    const float* ff    = (const float*)d_in[2];
    const float* bfeat = (const float*)d_in[3];
    const float* supp  = (const float*)d_in[4];
    const int*   fi    = (const int*)d_in[5];
    const int*   fj    = (const int*)d_in[6];
    const int*   bf    = (const int*)d_in[7];
    const int*   bb    = (const int*)d_in[8];
    const float* W0    = (const float*)d_in[9];
    const float* W1    = (const float*)d_in[10];
    const float* W2    = (const float*)d_in[11];
    const float* W3    = (const float*)d_in[12];
    const float* W4    = (const float*)d_in[13];
    const float* fc0   = (const float*)d_in[14];
    const float* fc1   = (const float*)d_in[15];
    const float* fc2   = (const float*)d_in[16];
    const float* fc3   = (const float*)d_in[17];
    float* out = (float*)d_out;

    const int SMEM_96 = 2560 + 2*(128*(96+8)*2);   // 55808
    const int SMEM_64 = 2560 + 2*(128*(64+8)*2);   // 39424
    static bool attrDone = false;
    if (!attrDone) {
        cudaFuncSetAttribute(k_mma<96>, cudaFuncAttributeMaxDynamicSharedMemorySize, SMEM_96);
        cudaFuncSetAttribute(k_mma<64>, cudaFuncAttributeMaxDynamicSharedMemorySize, SMEM_64);
        attrDone = true;
    }

    k_pre<<<1024, 256>>>(ff, W2, W3, fc0);
    k_count<<<NBLK_F + NBLK_B, 256>>>(fp, bp, supp, fi, fj, bf, bb);
    k_scan2<<<1, 1024>>>();
    k_fillA<<<NBLK_F + NBLK_B, 256>>>();

    k_front<<<T8F/8 + T8B/8, 256>>>(ff, W0, fi, fj, bfeat, W1, bf, bb);

    k_mma<96><<<NT128, 128, SMEM_96>>>(fi, fj);
    k_postB<<<NF/8, 256>>>(fc1);

    k_mma<64><<<NT128, 128, SMEM_64>>>(fi, fj);
    k_postC<<<NF/8, 256>>>(fc2);

    k_w4<<<T8F/8, 256>>>(W4, fi, fj);
    k_postD<<<NF/256, 256>>>(fc3, out);
}